// round 6
// baseline (speedup 1.0000x reference)
#include <cuda_runtime.h>
#include <cuda_fp16.h>
#include <math.h>
#include <stdint.h>

#define BATCH  4
#define SEQ    2048
#define EMB    2048
#define NHEAD  16
#define HDIM   128
#define MTOT   (BATCH*SEQ)      // 8192
#define KDIM   2048
#define NELEM_X (MTOT*KDIM)     // 16.8M
#define NELEM_W (KDIM*KDIM)     // 4.19M

// ---------------- scratch (device globals: allocation-free rule) ----------------
__device__ __half g_xh[NELEM_X],  g_xl[NELEM_X];
__device__ __half g_Wh[4][NELEM_W], g_Wl[4][NELEM_W];
__device__ __half g_Qh[NELEM_X], g_Ql[NELEM_X];
__device__ __half g_Kh[NELEM_X], g_Kl[NELEM_X];
__device__ __half g_Vh[NELEM_X], g_Vl[NELEM_X];
__device__ __half g_Ch[NELEM_X], g_Cl[NELEM_X];

__device__ __forceinline__ uint32_t smem_u32(const void* p) {
    uint32_t a;
    asm("{ .reg .u64 t; cvta.to.shared.u64 t, %1; cvt.u32.u64 %0, t; }" : "=r"(a) : "l"(p));
    return a;
}

#define CP_ASYNC16(dst, src) \
    asm volatile("cp.async.cg.shared.global [%0], [%1], 16;" :: "r"(dst), "l"(src))
#define CP_COMMIT() asm volatile("cp.async.commit_group;" ::: "memory")
#define CP_WAIT(n)  asm volatile("cp.async.wait_group %0;" :: "n"(n) : "memory")

#define LDMX4(r0,r1,r2,r3, addr) \
    asm volatile("ldmatrix.sync.aligned.m8n8.x4.shared.b16 {%0,%1,%2,%3}, [%4];" \
        : "=r"(r0),"=r"(r1),"=r"(r2),"=r"(r3) : "r"(addr))
#define LDMX4T(r0,r1,r2,r3, addr) \
    asm volatile("ldmatrix.sync.aligned.m8n8.x4.trans.shared.b16 {%0,%1,%2,%3}, [%4];" \
        : "=r"(r0),"=r"(r1),"=r"(r2),"=r"(r3) : "r"(addr))

#define MMA16816(c, a0,a1,a2,a3, b0,b1) \
    asm volatile("mma.sync.aligned.m16n8k16.row.col.f32.f16.f16.f32 " \
        "{%0,%1,%2,%3}, {%4,%5,%6,%7}, {%8,%9}, {%0,%1,%2,%3};" \
        : "+f"((c)[0]),"+f"((c)[1]),"+f"((c)[2]),"+f"((c)[3]) \
        : "r"(a0),"r"(a1),"r"(a2),"r"(a3), "r"(b0),"r"(b1))

__device__ __forceinline__ uint32_t pack_h2(__half x, __half y) {
    __half2 h = __halves2half2(x, y);
    return *(uint32_t*)&h;
}
__device__ __forceinline__ void split_hl(float x, float y, uint32_t& hp, uint32_t& lp) {
    __half hx = __float2half_rn(x), hy = __float2half_rn(y);
    hp = pack_h2(hx, hy);
    lp = pack_h2(__float2half_rn(x - __half2float(hx)),
                 __float2half_rn(y - __half2float(hy)));
}

// =================================================================================
// pre-convert: fp32 -> fp16 hi/lo (2 x float4 per thread for MLP)
// =================================================================================
__global__ void __launch_bounds__(256) conv_hl(
    const float* __restrict__ s, __half* __restrict__ h, __half* __restrict__ l)
{
    int i0 = blockIdx.x * 512 + threadIdx.x;
    #pragma unroll
    for (int k = 0; k < 2; k++) {
        int i = i0 + k * 256;
        float4 v = ((const float4*)s)[i];
        uint2 hp, lp;
        split_hl(v.x, v.y, hp.x, lp.x);
        split_hl(v.z, v.w, hp.y, lp.y);
        ((uint2*)h)[i] = hp;
        ((uint2*)l)[i] = lp;
    }
}

// =================================================================================
// fp16x3 mma GEMM: C[m,n] = sum_k A[m,k]*W[n,k]
// BM=128, BN=128, BK=64; 8 warps 2(M)x4(N) -> 64x32 warp tile;
// 3-stage cp.async ring, ONE syncthreads per stage.
// MODE 0: plain fp32 store.  MODE 1: QKV (z), RoPE for z<2, hi/lo fp16 [B,H,S,D].
// =================================================================================
#define BM 128
#define BN 128
#define BK 64
#define NSTG (KDIM/BK)     // 32

// per-stage smem (bytes): Ah 16K | Al 16K | Bh 16K | Bl 16K = 64K
#define GS_AH 0
#define GS_AL 16384
#define GS_BH 32768
#define GS_BL 49152
#define GS_STRIDE 65536
#define GSM (3*GS_STRIDE)   // 192KB

template<int MODE>
__global__ void __launch_bounds__(256, 1) gemm_hl(
    const __half* __restrict__ Ah, const __half* __restrict__ Al,
    const __half* __restrict__ Bh0, const __half* __restrict__ Bl0,
    const __half* __restrict__ Bh1, const __half* __restrict__ Bl1,
    const __half* __restrict__ Bh2, const __half* __restrict__ Bl2,
    __half* __restrict__ Dh0, __half* __restrict__ Dl0,
    __half* __restrict__ Dh1, __half* __restrict__ Dl1,
    __half* __restrict__ Dh2, __half* __restrict__ Dl2,
    float* __restrict__ Dout)
{
    extern __shared__ char sm[];
    const uint32_t sb = smem_u32(sm);

    const __half* Bh = Bh0;
    const __half* Bl = Bl0;
    int z = 0;
    if (MODE == 1) {
        z = blockIdx.z;
        if (z == 1) { Bh = Bh1; Bl = Bl1; }
        else if (z == 2) { Bh = Bh2; Bl = Bl2; }
    }

    const int tid = threadIdx.x;
    const int wid = tid >> 5;
    const int lid = tid & 31;
    const int wm = wid >> 2;        // 0..1 -> 64 rows each
    const int wn = wid & 3;         // 0..3 -> 32 cols each
    const int m0 = blockIdx.y * BM;
    const int n0 = blockIdx.x * BN;

    float acc[4][4][4];             // [m16 tile][n8 tile][frag]
    #pragma unroll
    for (int i = 0; i < 4; i++)
        #pragma unroll
        for (int j = 0; j < 4; j++)
            #pragma unroll
            for (int k = 0; k < 4; k++) acc[i][j][k] = 0.f;

    // 16 cp.async chunks per thread per stage (A hi/lo + B hi/lo, 1024 chunks each)
    auto issue_stage = [&](int s) {
        const int kt = s * BK;
        const uint32_t base = sb + (uint32_t)(s % 3) * GS_STRIDE;
        #pragma unroll
        for (int i = 0; i < 4; i++) {
            int c = i * 256 + tid;
            int r = c >> 3, c16 = c & 7;
            uint32_t off = (uint32_t)(r * 128 + c16 * 16);
            off ^= (off >> 3) & 0x70;
            const size_t ga = (size_t)(m0 + r) * KDIM + kt + c16 * 8;
            const size_t gb = (size_t)(n0 + r) * KDIM + kt + c16 * 8;
            CP_ASYNC16(base + GS_AH + off, Ah + ga);
            CP_ASYNC16(base + GS_AL + off, Al + ga);
            CP_ASYNC16(base + GS_BH + off, Bh + gb);
            CP_ASYNC16(base + GS_BL + off, Bl + gb);
        }
        CP_COMMIT();
    };

    auto compute_stage = [&](int s) {
        const uint32_t base = sb + (uint32_t)(s % 3) * GS_STRIDE;
        const int lr = lid & 15;
        const int lc = lid >> 4;
        #pragma unroll
        for (int ks = 0; ks < 4; ks++) {
            uint32_t bhf[2][4], blf[2][4];
            #pragma unroll
            for (int bt = 0; bt < 2; bt++) {
                uint32_t boff = (uint32_t)((wn * 32 + bt * 16 + lr) * 128 + ks * 32 + lc * 16);
                boff ^= (boff >> 3) & 0x70;
                LDMX4(bhf[bt][0], bhf[bt][1], bhf[bt][2], bhf[bt][3], base + GS_BH + boff);
                LDMX4(blf[bt][0], blf[bt][1], blf[bt][2], blf[bt][3], base + GS_BL + boff);
            }
            #pragma unroll
            for (int mt = 0; mt < 4; mt++) {
                uint32_t aoff = (uint32_t)((wm * 64 + mt * 16 + lr) * 128 + ks * 32 + lc * 16);
                aoff ^= (aoff >> 3) & 0x70;
                uint32_t a0, a1, a2, a3, q0, q1, q2, q3;
                LDMX4(a0, a1, a2, a3, base + GS_AH + aoff);
                LDMX4(q0, q1, q2, q3, base + GS_AL + aoff);
                #pragma unroll
                for (int bt = 0; bt < 2; bt++) {
                    MMA16816(acc[mt][bt * 2],     a0, a1, a2, a3, bhf[bt][0], bhf[bt][2]);
                    MMA16816(acc[mt][bt * 2],     a0, a1, a2, a3, blf[bt][0], blf[bt][2]);
                    MMA16816(acc[mt][bt * 2],     q0, q1, q2, q3, bhf[bt][0], bhf[bt][2]);
                    MMA16816(acc[mt][bt * 2 + 1], a0, a1, a2, a3, bhf[bt][1], bhf[bt][3]);
                    MMA16816(acc[mt][bt * 2 + 1], a0, a1, a2, a3, blf[bt][1], blf[bt][3]);
                    MMA16816(acc[mt][bt * 2 + 1], q0, q1, q2, q3, bhf[bt][1], bhf[bt][3]);
                }
            }
        }
    };

    issue_stage(0);
    issue_stage(1);
    for (int s = 0; s < NSTG; s++) {
        if (s + 2 < NSTG) CP_WAIT(1); else CP_WAIT(0);
        __syncthreads();            // stage s landed for ALL threads; also fences
                                    // everyone past compute(s-1) -> ring slot reuse safe
        compute_stage(s);
        if (s + 2 < NSTG) issue_stage(s + 2);
    }

    // ---------------- epilogue ----------------
    const int rrow = lid >> 2;
    const int cpair = (lid & 3) * 2;
    #pragma unroll
    for (int mt = 0; mt < 4; mt++) {
        #pragma unroll
        for (int j = 0; j < 4; j++) {
            int n = n0 + wn * 32 + j * 8 + cpair;
            if (MODE == 0) {
                #pragma unroll
                for (int hf = 0; hf < 2; hf++) {
                    int m = m0 + wm * 64 + mt * 16 + rrow + hf * 8;
                    *(float2*)(Dout + (size_t)m * EMB + n) =
                        make_float2(acc[mt][j][2 * hf], acc[mt][j][2 * hf + 1]);
                }
            } else {
                __half* Dh = (z == 0) ? Dh0 : (z == 1) ? Dh1 : Dh2;
                __half* Dl = (z == 0) ? Dl0 : (z == 1) ? Dl1 : Dl2;
                int h  = n >> 7;
                int dd = n & 127;
                float invf = powf(10000.0f, -(float)(dd >> 1) * (1.0f / 64.0f));
                #pragma unroll
                for (int hf = 0; hf < 2; hf++) {
                    int m = m0 + wm * 64 + mt * 16 + rrow + hf * 8;
                    int bb = m >> 11;
                    int sq = m & 2047;
                    float c0 = acc[mt][j][2 * hf], c1 = acc[mt][j][2 * hf + 1];
                    float v0 = c0, v1 = c1;
                    if (z < 2) {
                        float ang = (float)sq * invf;
                        float sn, cs;
                        sincosf(ang, &sn, &cs);
                        v0 = c0 * cs - c1 * sn;
                        v1 = c1 * cs + c0 * sn;
                    }
                    size_t idx = ((size_t)(bb * NHEAD + h) * SEQ + sq) * HDIM + dd;
                    uint32_t hp, lp;
                    split_hl(v0, v1, hp, lp);
                    *(uint32_t*)(Dh + idx) = hp;
                    *(uint32_t*)(Dl + idx) = lp;
                }
            }
        }
    }
}

// =================================================================================
// Flash attention, fp16x3 mma, pre-converted hi/lo inputs, K/V double-buffered.
// (unchanged from R5 - passing)
// =================================================================================
#define FQH 0
#define FQL 32768
#define FKV 65536
#define FKV_STRIDE 65536
#define FKH 0
#define FKL 16384
#define FVH 32768
#define FVL 49152
#define FH_BYTES 196608

__device__ __forceinline__ uint32_t sw256(uint32_t off) {
    return off ^ ((off >> 4) & 0x70);
}

__global__ void __launch_bounds__(256, 1) flash_mma(
    const __half* __restrict__ Qh, const __half* __restrict__ Ql,
    const __half* __restrict__ Kh, const __half* __restrict__ Kl,
    const __half* __restrict__ Vh, const __half* __restrict__ Vl,
    __half* __restrict__ Ch, __half* __restrict__ Cl)
{
    extern __shared__ char sm[];
    const uint32_t sb = smem_u32(sm);

    const int tid = threadIdx.x;
    const int wid = tid >> 5;
    const int lid = tid & 31;
    const int q0 = (gridDim.x - 1 - blockIdx.x) * 128;
    const int b  = blockIdx.y >> 4, h = blockIdx.y & 15;
    const size_t bh = ((size_t)(b * NHEAD + h)) * SEQ * HDIM;

    const int nIter = (q0 >> 6) + 2;

    auto issue_kv = [&](int it, int buf) {
        const int j0 = it * 64;
        const uint32_t base = sb + FKV + buf * FKV_STRIDE;
        #pragma unroll
        for (int i = 0; i < 4; i++) {
            int c = i * 256 + tid;
            int r = c >> 4, c16 = c & 15;
            uint32_t off = sw256((uint32_t)(r * 256 + c16 * 16));
            size_t src = bh + (size_t)(j0 + r) * HDIM + c16 * 8;
            CP_ASYNC16(base + FKH + off, Kh + src);
            CP_ASYNC16(base + FKL + off, Kl + src);
            CP_ASYNC16(base + FVH + off, Vh + src);
            CP_ASYNC16(base + FVL + off, Vl + src);
        }
        CP_COMMIT();
    };

    {
        #pragma unroll
        for (int i = 0; i < 8; i++) {
            int c = i * 256 + tid;
            int r = c >> 4, c16 = c & 15;
            uint32_t off = sw256((uint32_t)(r * 256 + c16 * 16));
            size_t src = bh + (size_t)(q0 + r) * HDIM + c16 * 8;
            CP_ASYNC16(sb + FQH + off, Qh + src);
            CP_ASYNC16(sb + FQL + off, Ql + src);
        }
    }
    issue_kv(0, 0);

    float os[16][4];
    #pragma unroll
    for (int i = 0; i < 16; i++)
        #pragma unroll
        for (int j = 0; j < 4; j++) os[i][j] = 0.f;
    float mrow[2] = {-1e30f, -1e30f};
    float lrow[2] = {0.f, 0.f};
    const float scale = 0.08838834764831845f;

    const int lr = lid & 15;
    const int lc = lid >> 4;

    for (int it = 0; it < nIter; it++) {
        const int j0 = it * 64;
        const int buf = it & 1;
        const uint32_t kbase = sb + FKV + buf * FKV_STRIDE;

        if (it + 1 < nIter) {
            issue_kv(it + 1, buf ^ 1);
            CP_WAIT(1);
        } else {
            CP_WAIT(0);
        }
        __syncthreads();

        if (j0 < q0 + (wid + 1) * 16) {
            float sacc[8][4];
            #pragma unroll
            for (int i = 0; i < 8; i++)
                #pragma unroll
                for (int j = 0; j < 4; j++) sacc[i][j] = 0.f;

            #pragma unroll
            for (int ks = 0; ks < 8; ks++) {
                uint32_t aoff = sw256((uint32_t)((wid * 16 + lr) * 256 + ks * 32 + lc * 16));
                uint32_t qh0, qh1, qh2, qh3, ql0, ql1, ql2, ql3;
                LDMX4(qh0, qh1, qh2, qh3, sb + FQH + aoff);
                LDMX4(ql0, ql1, ql2, ql3, sb + FQL + aoff);
                #pragma unroll
                for (int bg = 0; bg < 4; bg++) {
                    uint32_t boff = sw256((uint32_t)((bg * 16 + lr) * 256 + ks * 32 + lc * 16));
                    uint32_t kh0, kh1, kh2, kh3, kl0, kl1, kl2, kl3;
                    LDMX4(kh0, kh1, kh2, kh3, kbase + FKH + boff);
                    LDMX4(kl0, kl1, kl2, kl3, kbase + FKL + boff);
                    MMA16816(sacc[bg * 2],     qh0, qh1, qh2, qh3, kh0, kh2);
                    MMA16816(sacc[bg * 2],     qh0, qh1, qh2, qh3, kl0, kl2);
                    MMA16816(sacc[bg * 2],     ql0, ql1, ql2, ql3, kh0, kh2);
                    MMA16816(sacc[bg * 2 + 1], qh0, qh1, qh2, qh3, kh1, kh3);
                    MMA16816(sacc[bg * 2 + 1], qh0, qh1, qh2, qh3, kl1, kl3);
                    MMA16816(sacc[bg * 2 + 1], ql0, ql1, ql2, ql3, kh1, kh3);
                }
            }

            const int r0g = q0 + wid * 16 + (lid >> 2);
            const int c0g = j0 + 2 * (lid & 3);
            #pragma unroll
            for (int nt = 0; nt < 8; nt++)
                #pragma unroll
                for (int c = 0; c < 4; c++) {
                    int rr = r0g + ((c >= 2) ? 8 : 0);
                    int cc = c0g + nt * 8 + (c & 1);
                    float v = sacc[nt][c] * scale;
                    if (cc > rr) v = -1e30f;
                    sacc[nt][c] = v;
                }

            float mx0 = -1e30f, mx1 = -1e30f;
            #pragma unroll
            for (int nt = 0; nt < 8; nt++) {
                mx0 = fmaxf(mx0, fmaxf(sacc[nt][0], sacc[nt][1]));
                mx1 = fmaxf(mx1, fmaxf(sacc[nt][2], sacc[nt][3]));
            }
            #pragma unroll
            for (int o = 1; o < 4; o <<= 1) {
                mx0 = fmaxf(mx0, __shfl_xor_sync(0xffffffffu, mx0, o));
                mx1 = fmaxf(mx1, __shfl_xor_sync(0xffffffffu, mx1, o));
            }
            float mn0 = fmaxf(mrow[0], mx0);
            float mn1 = fmaxf(mrow[1], mx1);
            float cr0 = __expf(mrow[0] - mn0);
            float cr1 = __expf(mrow[1] - mn1);
            float rs0 = 0.f, rs1 = 0.f;
            #pragma unroll
            for (int nt = 0; nt < 8; nt++) {
                float p0 = __expf(sacc[nt][0] - mn0);
                float p1 = __expf(sacc[nt][1] - mn0);
                float p2 = __expf(sacc[nt][2] - mn1);
                float p3 = __expf(sacc[nt][3] - mn1);
                sacc[nt][0] = p0; sacc[nt][1] = p1; sacc[nt][2] = p2; sacc[nt][3] = p3;
                rs0 += p0 + p1; rs1 += p2 + p3;
            }
            #pragma unroll
            for (int o = 1; o < 4; o <<= 1) {
                rs0 += __shfl_xor_sync(0xffffffffu, rs0, o);
                rs1 += __shfl_xor_sync(0xffffffffu, rs1, o);
            }
            lrow[0] = lrow[0] * cr0 + rs0;
            lrow[1] = lrow[1] * cr1 + rs1;
            mrow[0] = mn0; mrow[1] = mn1;
            #pragma unroll
            for (int nt = 0; nt < 16; nt++) {
                os[nt][0] *= cr0; os[nt][1] *= cr0;
                os[nt][2] *= cr1; os[nt][3] *= cr1;
            }

            #pragma unroll
            for (int kt = 0; kt < 4; kt++) {
                uint32_t ah[4], al[4];
                #pragma unroll
                for (int q = 0; q < 4; q++) {
                    int nt = 2 * kt + (q >> 1);
                    int cc = (q & 1) * 2;
                    split_hl(sacc[nt][cc], sacc[nt][cc + 1], ah[q], al[q]);
                }
                const int vrow = kt * 16 + (lid & 7) + ((lid >> 3) & 1) * 8;
                const int vnh  = (lid >> 4) * 8;
                #pragma unroll
                for (int bg2 = 0; bg2 < 8; bg2++) {
                    uint32_t voff = sw256((uint32_t)(vrow * 256 + (bg2 * 16 + vnh) * 2));
                    uint32_t vh0, vh1, vh2, vh3, vl0, vl1, vl2, vl3;
                    LDMX4T(vh0, vh1, vh2, vh3, kbase + FVH + voff);
                    LDMX4T(vl0, vl1, vl2, vl3, kbase + FVL + voff);
                    MMA16816(os[bg2 * 2],     ah[0], ah[1], ah[2], ah[3], vh0, vh1);
                    MMA16816(os[bg2 * 2],     ah[0], ah[1], ah[2], ah[3], vl0, vl1);
                    MMA16816(os[bg2 * 2],     al[0], al[1], al[2], al[3], vh0, vh1);
                    MMA16816(os[bg2 * 2 + 1], ah[0], ah[1], ah[2], ah[3], vh2, vh3);
                    MMA16816(os[bg2 * 2 + 1], ah[0], ah[1], ah[2], ah[3], vl2, vl3);
                    MMA16816(os[bg2 * 2 + 1], al[0], al[1], al[2], al[3], vh2, vh3);
                }
            }
        }
        __syncthreads();
    }

    const float inv0 = 1.0f / lrow[0];
    const float inv1 = 1.0f / lrow[1];
    const int row0 = q0 + wid * 16 + (lid >> 2);
    const int dbase = 2 * (lid & 3);
    #pragma unroll
    for (int nt = 0; nt < 16; nt++) {
        int d = nt * 8 + dbase;
        size_t i0 = ((size_t)(b * SEQ + row0))     * EMB + h * HDIM + d;
        size_t i1 = ((size_t)(b * SEQ + row0 + 8)) * EMB + h * HDIM + d;
        uint32_t hp, lp;
        split_hl(os[nt][0] * inv0, os[nt][1] * inv0, hp, lp);
        *(uint32_t*)(Ch + i0) = hp;
        *(uint32_t*)(Cl + i0) = lp;
        split_hl(os[nt][2] * inv1, os[nt][3] * inv1, hp, lp);
        *(uint32_t*)(Ch + i1) = hp;
        *(uint32_t*)(Cl + i1) = lp;
    }
}

// =================================================================================
extern "C" void kernel_launch(void* const* d_in, const int* in_sizes, int n_in,
                              void* d_out, int out_size)
{
    const float* x  = (const float*)d_in[0];
    const float* Wq = (const float*)d_in[1];
    const float* Wk = (const float*)d_in[2];
    const float* Wv = (const float*)d_in[3];
    const float* Wo = (const float*)d_in[4];
    float* out = (float*)d_out;

    __half *xh, *xl, *Wh, *Wl, *Qh, *Ql, *Kh, *Kl, *Vh, *Vl, *Ch, *Cl;
    cudaGetSymbolAddress((void**)&xh, g_xh);
    cudaGetSymbolAddress((void**)&xl, g_xl);
    cudaGetSymbolAddress((void**)&Wh, g_Wh);
    cudaGetSymbolAddress((void**)&Wl, g_Wl);
    cudaGetSymbolAddress((void**)&Qh, g_Qh);
    cudaGetSymbolAddress((void**)&Ql, g_Ql);
    cudaGetSymbolAddress((void**)&Kh, g_Kh);
    cudaGetSymbolAddress((void**)&Kl, g_Kl);
    cudaGetSymbolAddress((void**)&Vh, g_Vh);
    cudaGetSymbolAddress((void**)&Vl, g_Vl);
    cudaGetSymbolAddress((void**)&Ch, g_Ch);
    cudaGetSymbolAddress((void**)&Cl, g_Cl);

    cudaFuncSetAttribute(gemm_hl<1>, cudaFuncAttributeMaxDynamicSharedMemorySize, GSM);
    cudaFuncSetAttribute(gemm_hl<0>, cudaFuncAttributeMaxDynamicSharedMemorySize, GSM);
    cudaFuncSetAttribute(flash_mma, cudaFuncAttributeMaxDynamicSharedMemorySize, FH_BYTES);

    // 0) pre-convert inputs to fp16 hi/lo
    conv_hl<<<NELEM_X / 2048, 256>>>(x,  xh, xl);
    conv_hl<<<NELEM_W / 2048, 256>>>(Wq, Wh + 0 * NELEM_W, Wl + 0 * NELEM_W);
    conv_hl<<<NELEM_W / 2048, 256>>>(Wk, Wh + 1 * NELEM_W, Wl + 1 * NELEM_W);
    conv_hl<<<NELEM_W / 2048, 256>>>(Wv, Wh + 2 * NELEM_W, Wl + 2 * NELEM_W);
    conv_hl<<<NELEM_W / 2048, 256>>>(Wo, Wh + 3 * NELEM_W, Wl + 3 * NELEM_W);

    // 1) fused QKV projection + RoPE -> hi/lo [B,H,S,D]
    {
        dim3 grid(EMB / BN, MTOT / BM, 3);
        gemm_hl<1><<<grid, 256, GSM>>>(
            xh, xl,
            Wh + 0 * NELEM_W, Wl + 0 * NELEM_W,
            Wh + 1 * NELEM_W, Wl + 1 * NELEM_W,
            Wh + 2 * NELEM_W, Wl + 2 * NELEM_W,
            Qh, Ql, Kh, Kl, Vh, Vl, nullptr);
    }
    // 2) causal flash attention -> context hi/lo
    {
        dim3 grid(SEQ / 128, BATCH * NHEAD);
        flash_mma<<<grid, 256, FH_BYTES>>>(Qh, Ql, Kh, Kl, Vh, Vl, Ch, Cl);
    }
    // 3) output projection -> fp32 out
    {
        dim3 grid(EMB / BN, MTOT / BM, 1);
        gemm_hl<0><<<grid, 256, GSM>>>(
            Ch, Cl,
            Wh + 3 * NELEM_W, Wl + 3 * NELEM_W,
            nullptr, nullptr, nullptr, nullptr,
            nullptr, nullptr, nullptr, nullptr, nullptr, nullptr, out);
    }
}

// round 7
// speedup vs baseline: 1.0359x; 1.0359x over previous
#include <cuda_runtime.h>
#include <cuda_fp16.h>
#include <math.h>
#include <stdint.h>

#define BATCH  4
#define SEQ    2048
#define EMB    2048
#define NHEAD  16
#define HDIM   128
#define MTOT   (BATCH*SEQ)      // 8192
#define KDIM   2048
#define NELEM_X (MTOT*KDIM)     // 16.8M
#define NELEM_W (KDIM*KDIM)     // 4.19M

// ---------------- scratch (device globals: allocation-free rule) ----------------
__device__ __half g_xh[NELEM_X],  g_xl[NELEM_X];
__device__ __half g_Wh[4][NELEM_W], g_Wl[4][NELEM_W];
__device__ __half g_Qh[NELEM_X], g_Ql[NELEM_X];
__device__ __half g_Kh[NELEM_X], g_Kl[NELEM_X];
__device__ __half g_Vh[NELEM_X], g_Vl[NELEM_X];
__device__ __half g_Ch[NELEM_X], g_Cl[NELEM_X];

__device__ __forceinline__ uint32_t smem_u32(const void* p) {
    uint32_t a;
    asm("{ .reg .u64 t; cvta.to.shared.u64 t, %1; cvt.u32.u64 %0, t; }" : "=r"(a) : "l"(p));
    return a;
}

#define CP_ASYNC16(dst, src) \
    asm volatile("cp.async.cg.shared.global [%0], [%1], 16;" :: "r"(dst), "l"(src))
#define CP_COMMIT() asm volatile("cp.async.commit_group;" ::: "memory")
#define CP_WAIT(n)  asm volatile("cp.async.wait_group %0;" :: "n"(n) : "memory")

#define LDMX4(r0,r1,r2,r3, addr) \
    asm volatile("ldmatrix.sync.aligned.m8n8.x4.shared.b16 {%0,%1,%2,%3}, [%4];" \
        : "=r"(r0),"=r"(r1),"=r"(r2),"=r"(r3) : "r"(addr))
#define LDMX4T(r0,r1,r2,r3, addr) \
    asm volatile("ldmatrix.sync.aligned.m8n8.x4.trans.shared.b16 {%0,%1,%2,%3}, [%4];" \
        : "=r"(r0),"=r"(r1),"=r"(r2),"=r"(r3) : "r"(addr))

#define MMA16816(c, a0,a1,a2,a3, b0,b1) \
    asm volatile("mma.sync.aligned.m16n8k16.row.col.f32.f16.f16.f32 " \
        "{%0,%1,%2,%3}, {%4,%5,%6,%7}, {%8,%9}, {%0,%1,%2,%3};" \
        : "+f"((c)[0]),"+f"((c)[1]),"+f"((c)[2]),"+f"((c)[3]) \
        : "r"(a0),"r"(a1),"r"(a2),"r"(a3), "r"(b0),"r"(b1))

__device__ __forceinline__ uint32_t pack_h2(__half x, __half y) {
    __half2 h = __halves2half2(x, y);
    return *(uint32_t*)&h;
}
__device__ __forceinline__ void split_hl(float x, float y, uint32_t& hp, uint32_t& lp) {
    __half hx = __float2half_rn(x), hy = __float2half_rn(y);
    hp = pack_h2(hx, hy);
    lp = pack_h2(__float2half_rn(x - __half2float(hx)),
                 __float2half_rn(y - __half2float(hy)));
}

// =================================================================================
// fused pre-convert: one launch converts x + Wq + Wk + Wv + Wo to fp16 hi/lo.
// block-index dispatch; 2 x float4 per thread.
// =================================================================================
#define XB (NELEM_X/2048)   // 8192 blocks for x
#define WB (NELEM_W/2048)   // 2048 blocks per W

__global__ void __launch_bounds__(256) conv_all(
    const float* __restrict__ x,
    const float* __restrict__ Wq, const float* __restrict__ Wk,
    const float* __restrict__ Wv, const float* __restrict__ Wo,
    __half* __restrict__ xh, __half* __restrict__ xl,
    __half* __restrict__ Wh, __half* __restrict__ Wl)
{
    const float* s;
    __half *h, *l;
    int blk = blockIdx.x;
    if (blk < XB) {
        s = x; h = xh; l = xl;
    } else {
        int wi = (blk - XB) / WB;
        blk = (blk - XB) % WB;
        s = (wi == 0) ? Wq : (wi == 1) ? Wk : (wi == 2) ? Wv : Wo;
        h = Wh + (size_t)wi * NELEM_W;
        l = Wl + (size_t)wi * NELEM_W;
    }
    int i0 = blk * 512 + threadIdx.x;
    #pragma unroll
    for (int k = 0; k < 2; k++) {
        int i = i0 + k * 256;
        float4 v = ((const float4*)s)[i];
        uint2 hp, lp;
        split_hl(v.x, v.y, hp.x, lp.x);
        split_hl(v.z, v.w, hp.y, lp.y);
        ((uint2*)h)[i] = hp;
        ((uint2*)l)[i] = lp;
    }
}

// =================================================================================
// fp16x3 mma GEMM (R5 shape: BM=128, BN=64, BK=64, 2 CTAs/SM, 2-stage)
// MODE 0: plain fp32 store.  MODE 1: QKV (z), RoPE for z<2, hi/lo fp16 [B,H,S,D].
// =================================================================================
#define BM 128
#define BN 64
#define BK 64
#define NSTG (KDIM/BK)     // 32

// per-stage smem: Ah 16K | Al 16K | Bh 8K | Bl 8K = 48K
#define GS_AH 0
#define GS_AL 16384
#define GS_BH 32768
#define GS_BL 40960
#define GS_STRIDE 49152
#define GSM (2*GS_STRIDE)   // 96KB

template<int MODE>
__global__ void __launch_bounds__(256, 2) gemm_hl(
    const __half* __restrict__ Ah, const __half* __restrict__ Al,
    const __half* __restrict__ Bh0, const __half* __restrict__ Bl0,
    const __half* __restrict__ Bh1, const __half* __restrict__ Bl1,
    const __half* __restrict__ Bh2, const __half* __restrict__ Bl2,
    __half* __restrict__ Dh0, __half* __restrict__ Dl0,
    __half* __restrict__ Dh1, __half* __restrict__ Dl1,
    __half* __restrict__ Dh2, __half* __restrict__ Dl2,
    float* __restrict__ Dout)
{
    extern __shared__ char sm[];
    const uint32_t sb = smem_u32(sm);

    const __half* Bh = Bh0;
    const __half* Bl = Bl0;
    int z = 0;
    if (MODE == 1) {
        z = blockIdx.z;
        if (z == 1) { Bh = Bh1; Bl = Bl1; }
        else if (z == 2) { Bh = Bh2; Bl = Bl2; }
    }

    const int tid = threadIdx.x;
    const int wid = tid >> 5;
    const int lid = tid & 31;
    const int wm = wid >> 2;
    const int wn = wid & 3;
    const int m0 = blockIdx.y * BM;
    const int n0 = blockIdx.x * BN;

    float acc[4][2][4];
    #pragma unroll
    for (int i = 0; i < 4; i++)
        #pragma unroll
        for (int j = 0; j < 2; j++)
            #pragma unroll
            for (int k = 0; k < 4; k++) acc[i][j][k] = 0.f;

    auto issue_stage = [&](int s) {
        const int kt = s * BK;
        const uint32_t base = sb + (s & 1) * GS_STRIDE;
        #pragma unroll
        for (int i = 0; i < 4; i++) {
            int c = i * 256 + tid;
            int r = c >> 3, c16 = c & 7;
            uint32_t off = (uint32_t)(r * 128 + c16 * 16);
            off ^= (off >> 3) & 0x70;
            const __half* srcH = Ah + (size_t)(m0 + r) * KDIM + kt + c16 * 8;
            const __half* srcL = Al + (size_t)(m0 + r) * KDIM + kt + c16 * 8;
            CP_ASYNC16(base + GS_AH + off, srcH);
            CP_ASYNC16(base + GS_AL + off, srcL);
        }
        #pragma unroll
        for (int i = 0; i < 2; i++) {
            int c = i * 256 + tid;
            int r = c >> 3, c16 = c & 7;
            uint32_t off = (uint32_t)(r * 128 + c16 * 16);
            off ^= (off >> 3) & 0x70;
            const __half* srcH = Bh + (size_t)(n0 + r) * KDIM + kt + c16 * 8;
            const __half* srcL = Bl + (size_t)(n0 + r) * KDIM + kt + c16 * 8;
            CP_ASYNC16(base + GS_BH + off, srcH);
            CP_ASYNC16(base + GS_BL + off, srcL);
        }
        CP_COMMIT();
    };

    auto compute_stage = [&](int s) {
        const uint32_t base = sb + (s & 1) * GS_STRIDE;
        const int lr = lid & 15;
        const int lc = lid >> 4;
        #pragma unroll
        for (int ks = 0; ks < 4; ks++) {
            uint32_t boff = (uint32_t)((wn * 16 + lr) * 128 + ks * 32 + lc * 16);
            boff ^= (boff >> 3) & 0x70;
            uint32_t bh0, bh1, bh2, bh3, bl0, bl1, bl2, bl3;
            LDMX4(bh0, bh1, bh2, bh3, base + GS_BH + boff);
            LDMX4(bl0, bl1, bl2, bl3, base + GS_BL + boff);
            #pragma unroll
            for (int mt = 0; mt < 4; mt++) {
                uint32_t aoff = (uint32_t)((wm * 64 + mt * 16 + lr) * 128 + ks * 32 + lc * 16);
                aoff ^= (aoff >> 3) & 0x70;
                uint32_t a0, a1, a2, a3, q0, q1, q2, q3;
                LDMX4(a0, a1, a2, a3, base + GS_AH + aoff);
                LDMX4(q0, q1, q2, q3, base + GS_AL + aoff);
                MMA16816(acc[mt][0], a0, a1, a2, a3, bh0, bh2);
                MMA16816(acc[mt][0], a0, a1, a2, a3, bl0, bl2);
                MMA16816(acc[mt][0], q0, q1, q2, q3, bh0, bh2);
                MMA16816(acc[mt][1], a0, a1, a2, a3, bh1, bh3);
                MMA16816(acc[mt][1], a0, a1, a2, a3, bl1, bl3);
                MMA16816(acc[mt][1], q0, q1, q2, q3, bh1, bh3);
            }
        }
    };

    issue_stage(0);
    for (int s = 0; s < NSTG; s++) {
        if (s + 1 < NSTG) {
            issue_stage(s + 1);
            CP_WAIT(1);
        } else {
            CP_WAIT(0);
        }
        __syncthreads();
        compute_stage(s);
        __syncthreads();
    }

    // ---------------- epilogue ----------------
    const int rrow = lid >> 2;
    const int cpair = (lid & 3) * 2;
    #pragma unroll
    for (int mt = 0; mt < 4; mt++) {
        #pragma unroll
        for (int nt = 0; nt < 2; nt++) {
            int n = n0 + wn * 16 + nt * 8 + cpair;
            if (MODE == 0) {
                #pragma unroll
                for (int hf = 0; hf < 2; hf++) {
                    int m = m0 + wm * 64 + mt * 16 + rrow + hf * 8;
                    *(float2*)(Dout + (size_t)m * EMB + n) =
                        make_float2(acc[mt][nt][2 * hf], acc[mt][nt][2 * hf + 1]);
                }
            } else {
                __half* Dh = (z == 0) ? Dh0 : (z == 1) ? Dh1 : Dh2;
                __half* Dl = (z == 0) ? Dl0 : (z == 1) ? Dl1 : Dl2;
                int h  = n >> 7;
                int dd = n & 127;
                float invf = powf(10000.0f, -(float)(dd >> 1) * (1.0f / 64.0f));
                #pragma unroll
                for (int hf = 0; hf < 2; hf++) {
                    int m = m0 + wm * 64 + mt * 16 + rrow + hf * 8;
                    int bb = m >> 11;
                    int sq = m & 2047;
                    float c0 = acc[mt][nt][2 * hf], c1 = acc[mt][nt][2 * hf + 1];
                    float v0 = c0, v1 = c1;
                    if (z < 2) {
                        float ang = (float)sq * invf;
                        float sn, cs;
                        sincosf(ang, &sn, &cs);
                        v0 = c0 * cs - c1 * sn;
                        v1 = c1 * cs + c0 * sn;
                    }
                    size_t idx = ((size_t)(bb * NHEAD + h) * SEQ + sq) * HDIM + dd;
                    uint32_t hp, lp;
                    split_hl(v0, v1, hp, lp);
                    *(uint32_t*)(Dh + idx) = hp;
                    *(uint32_t*)(Dl + idx) = lp;
                }
            }
        }
    }
}

// =================================================================================
// Flash attention, fp16x3 mma, hi/lo inputs, K/V double-buffered.
// R5 structure + warp-uniform causal skips at bg (QK) and kt (PV) granularity.
// =================================================================================
#define FQH 0
#define FQL 32768
#define FKV 65536
#define FKV_STRIDE 65536
#define FKH 0
#define FKL 16384
#define FVH 32768
#define FVL 49152
#define FH_BYTES 196608

__device__ __forceinline__ uint32_t sw256(uint32_t off) {
    return off ^ ((off >> 4) & 0x70);
}

__global__ void __launch_bounds__(256, 1) flash_mma(
    const __half* __restrict__ Qh, const __half* __restrict__ Ql,
    const __half* __restrict__ Kh, const __half* __restrict__ Kl,
    const __half* __restrict__ Vh, const __half* __restrict__ Vl,
    __half* __restrict__ Ch, __half* __restrict__ Cl)
{
    extern __shared__ char sm[];
    const uint32_t sb = smem_u32(sm);

    const int tid = threadIdx.x;
    const int wid = tid >> 5;
    const int lid = tid & 31;
    const int q0 = (gridDim.x - 1 - blockIdx.x) * 128;   // longest first
    const int b  = blockIdx.y >> 4, h = blockIdx.y & 15;
    const size_t bh = ((size_t)(b * NHEAD + h)) * SEQ * HDIM;

    const int nIter = (q0 >> 6) + 2;
    const int rmax = q0 + wid * 16 + 15;   // this warp's last (largest) q row

    auto issue_kv = [&](int it, int buf) {
        const int j0 = it * 64;
        const uint32_t base = sb + FKV + buf * FKV_STRIDE;
        #pragma unroll
        for (int i = 0; i < 4; i++) {
            int c = i * 256 + tid;
            int r = c >> 4, c16 = c & 15;
            uint32_t off = sw256((uint32_t)(r * 256 + c16 * 16));
            size_t src = bh + (size_t)(j0 + r) * HDIM + c16 * 8;
            CP_ASYNC16(base + FKH + off, Kh + src);
            CP_ASYNC16(base + FKL + off, Kl + src);
            CP_ASYNC16(base + FVH + off, Vh + src);
            CP_ASYNC16(base + FVL + off, Vl + src);
        }
        CP_COMMIT();
    };

    {
        #pragma unroll
        for (int i = 0; i < 8; i++) {
            int c = i * 256 + tid;
            int r = c >> 4, c16 = c & 15;
            uint32_t off = sw256((uint32_t)(r * 256 + c16 * 16));
            size_t src = bh + (size_t)(q0 + r) * HDIM + c16 * 8;
            CP_ASYNC16(sb + FQH + off, Qh + src);
            CP_ASYNC16(sb + FQL + off, Ql + src);
        }
    }
    issue_kv(0, 0);

    float os[16][4];
    #pragma unroll
    for (int i = 0; i < 16; i++)
        #pragma unroll
        for (int j = 0; j < 4; j++) os[i][j] = 0.f;
    float mrow[2] = {-1e30f, -1e30f};
    float lrow[2] = {0.f, 0.f};
    const float scale = 0.08838834764831845f;

    const int lr = lid & 15;
    const int lc = lid >> 4;

    for (int it = 0; it < nIter; it++) {
        const int j0 = it * 64;
        const int buf = it & 1;
        const uint32_t kbase = sb + FKV + buf * FKV_STRIDE;

        if (it + 1 < nIter) {
            issue_kv(it + 1, buf ^ 1);
            CP_WAIT(1);
        } else {
            CP_WAIT(0);
        }
        __syncthreads();

        if (j0 <= rmax) {
            float sacc[8][4];
            #pragma unroll
            for (int i = 0; i < 8; i++)
                #pragma unroll
                for (int j = 0; j < 4; j++) sacc[i][j] = 0.f;

            #pragma unroll
            for (int ks = 0; ks < 8; ks++) {
                uint32_t aoff = sw256((uint32_t)((wid * 16 + lr) * 256 + ks * 32 + lc * 16));
                uint32_t qh0, qh1, qh2, qh3, ql0, ql1, ql2, ql3;
                LDMX4(qh0, qh1, qh2, qh3, sb + FQH + aoff);
                LDMX4(ql0, ql1, ql2, ql3, sb + FQL + aoff);
                #pragma unroll
                for (int bg = 0; bg < 4; bg++) {
                    if (j0 + bg * 16 > rmax) continue;     // fully-masked col tile
                    uint32_t boff = sw256((uint32_t)((bg * 16 + lr) * 256 + ks * 32 + lc * 16));
                    uint32_t kh0, kh1, kh2, kh3, kl0, kl1, kl2, kl3;
                    LDMX4(kh0, kh1, kh2, kh3, kbase + FKH + boff);
                    LDMX4(kl0, kl1, kl2, kl3, kbase + FKL + boff);
                    MMA16816(sacc[bg * 2],     qh0, qh1, qh2, qh3, kh0, kh2);
                    MMA16816(sacc[bg * 2],     qh0, qh1, qh2, qh3, kl0, kl2);
                    MMA16816(sacc[bg * 2],     ql0, ql1, ql2, ql3, kh0, kh2);
                    MMA16816(sacc[bg * 2 + 1], qh0, qh1, qh2, qh3, kh1, kh3);
                    MMA16816(sacc[bg * 2 + 1], qh0, qh1, qh2, qh3, kl1, kl3);
                    MMA16816(sacc[bg * 2 + 1], ql0, ql1, ql2, ql3, kh1, kh3);
                }
            }

            const int r0g = q0 + wid * 16 + (lid >> 2);
            const int c0g = j0 + 2 * (lid & 3);
            #pragma unroll
            for (int nt = 0; nt < 8; nt++)
                #pragma unroll
                for (int c = 0; c < 4; c++) {
                    int rr = r0g + ((c >= 2) ? 8 : 0);
                    int cc = c0g + nt * 8 + (c & 1);
                    float v = sacc[nt][c] * scale;
                    if (cc > rr) v = -1e30f;
                    sacc[nt][c] = v;
                }

            float mx0 = -1e30f, mx1 = -1e30f;
            #pragma unroll
            for (int nt = 0; nt < 8; nt++) {
                mx0 = fmaxf(mx0, fmaxf(sacc[nt][0], sacc[nt][1]));
                mx1 = fmaxf(mx1, fmaxf(sacc[nt][2], sacc[nt][3]));
            }
            #pragma unroll
            for (int o = 1; o < 4; o <<= 1) {
                mx0 = fmaxf(mx0, __shfl_xor_sync(0xffffffffu, mx0, o));
                mx1 = fmaxf(mx1, __shfl_xor_sync(0xffffffffu, mx1, o));
            }
            float mn0 = fmaxf(mrow[0], mx0);
            float mn1 = fmaxf(mrow[1], mx1);
            float cr0 = __expf(mrow[0] - mn0);
            float cr1 = __expf(mrow[1] - mn1);
            float rs0 = 0.f, rs1 = 0.f;
            #pragma unroll
            for (int nt = 0; nt < 8; nt++) {
                float p0 = __expf(sacc[nt][0] - mn0);
                float p1 = __expf(sacc[nt][1] - mn0);
                float p2 = __expf(sacc[nt][2] - mn1);
                float p3 = __expf(sacc[nt][3] - mn1);
                sacc[nt][0] = p0; sacc[nt][1] = p1; sacc[nt][2] = p2; sacc[nt][3] = p3;
                rs0 += p0 + p1; rs1 += p2 + p3;
            }
            #pragma unroll
            for (int o = 1; o < 4; o <<= 1) {
                rs0 += __shfl_xor_sync(0xffffffffu, rs0, o);
                rs1 += __shfl_xor_sync(0xffffffffu, rs1, o);
            }
            lrow[0] = lrow[0] * cr0 + rs0;
            lrow[1] = lrow[1] * cr1 + rs1;
            mrow[0] = mn0; mrow[1] = mn1;
            #pragma unroll
            for (int nt = 0; nt < 16; nt++) {
                os[nt][0] *= cr0; os[nt][1] *= cr0;
                os[nt][2] *= cr1; os[nt][3] *= cr1;
            }

            #pragma unroll
            for (int kt = 0; kt < 4; kt++) {
                if (j0 + kt * 16 > rmax) continue;         // P tile exactly zero
                uint32_t ah[4], al[4];
                #pragma unroll
                for (int q = 0; q < 4; q++) {
                    int nt = 2 * kt + (q >> 1);
                    int cc = (q & 1) * 2;
                    split_hl(sacc[nt][cc], sacc[nt][cc + 1], ah[q], al[q]);
                }
                const int vrow = kt * 16 + (lid & 7) + ((lid >> 3) & 1) * 8;
                const int vnh  = (lid >> 4) * 8;
                #pragma unroll
                for (int bg2 = 0; bg2 < 8; bg2++) {
                    uint32_t voff = sw256((uint32_t)(vrow * 256 + (bg2 * 16 + vnh) * 2));
                    uint32_t vh0, vh1, vh2, vh3, vl0, vl1, vl2, vl3;
                    LDMX4T(vh0, vh1, vh2, vh3, kbase + FVH + voff);
                    LDMX4T(vl0, vl1, vl2, vl3, kbase + FVL + voff);
                    MMA16816(os[bg2 * 2],     ah[0], ah[1], ah[2], ah[3], vh0, vh1);
                    MMA16816(os[bg2 * 2],     ah[0], ah[1], ah[2], ah[3], vl0, vl1);
                    MMA16816(os[bg2 * 2],     al[0], al[1], al[2], al[3], vh0, vh1);
                    MMA16816(os[bg2 * 2 + 1], ah[0], ah[1], ah[2], ah[3], vh2, vh3);
                    MMA16816(os[bg2 * 2 + 1], ah[0], ah[1], ah[2], ah[3], vl2, vl3);
                    MMA16816(os[bg2 * 2 + 1], al[0], al[1], al[2], al[3], vh2, vh3);
                }
            }
        }
        __syncthreads();
    }

    const float inv0 = 1.0f / lrow[0];
    const float inv1 = 1.0f / lrow[1];
    const int row0 = q0 + wid * 16 + (lid >> 2);
    const int dbase = 2 * (lid & 3);
    #pragma unroll
    for (int nt = 0; nt < 16; nt++) {
        int d = nt * 8 + dbase;
        size_t i0 = ((size_t)(b * SEQ + row0))     * EMB + h * HDIM + d;
        size_t i1 = ((size_t)(b * SEQ + row0 + 8)) * EMB + h * HDIM + d;
        uint32_t hp, lp;
        split_hl(os[nt][0] * inv0, os[nt][1] * inv0, hp, lp);
        *(uint32_t*)(Ch + i0) = hp;
        *(uint32_t*)(Cl + i0) = lp;
        split_hl(os[nt][2] * inv1, os[nt][3] * inv1, hp, lp);
        *(uint32_t*)(Ch + i1) = hp;
        *(uint32_t*)(Cl + i1) = lp;
    }
}

// =================================================================================
extern "C" void kernel_launch(void* const* d_in, const int* in_sizes, int n_in,
                              void* d_out, int out_size)
{
    const float* x  = (const float*)d_in[0];
    const float* Wq = (const float*)d_in[1];
    const float* Wk = (const float*)d_in[2];
    const float* Wv = (const float*)d_in[3];
    const float* Wo = (const float*)d_in[4];
    float* out = (float*)d_out;

    __half *xh, *xl, *Wh, *Wl, *Qh, *Ql, *Kh, *Kl, *Vh, *Vl, *Ch, *Cl;
    cudaGetSymbolAddress((void**)&xh, g_xh);
    cudaGetSymbolAddress((void**)&xl, g_xl);
    cudaGetSymbolAddress((void**)&Wh, g_Wh);
    cudaGetSymbolAddress((void**)&Wl, g_Wl);
    cudaGetSymbolAddress((void**)&Qh, g_Qh);
    cudaGetSymbolAddress((void**)&Ql, g_Ql);
    cudaGetSymbolAddress((void**)&Kh, g_Kh);
    cudaGetSymbolAddress((void**)&Kl, g_Kl);
    cudaGetSymbolAddress((void**)&Vh, g_Vh);
    cudaGetSymbolAddress((void**)&Vl, g_Vl);
    cudaGetSymbolAddress((void**)&Ch, g_Ch);
    cudaGetSymbolAddress((void**)&Cl, g_Cl);

    cudaFuncSetAttribute(gemm_hl<1>, cudaFuncAttributeMaxDynamicSharedMemorySize, GSM);
    cudaFuncSetAttribute(gemm_hl<0>, cudaFuncAttributeMaxDynamicSharedMemorySize, GSM);
    cudaFuncSetAttribute(flash_mma, cudaFuncAttributeMaxDynamicSharedMemorySize, FH_BYTES);

    // 0) single fused pre-convert (x + 4 W)
    conv_all<<<XB + 4 * WB, 256>>>(x, Wq, Wk, Wv, Wo, xh, xl, Wh, Wl);

    // 1) fused QKV projection + RoPE -> hi/lo [B,H,S,D]
    {
        dim3 grid(EMB / BN, MTOT / BM, 3);
        gemm_hl<1><<<grid, 256, GSM>>>(
            xh, xl,
            Wh + 0 * (size_t)NELEM_W, Wl + 0 * (size_t)NELEM_W,
            Wh + 1 * (size_t)NELEM_W, Wl + 1 * (size_t)NELEM_W,
            Wh + 2 * (size_t)NELEM_W, Wl + 2 * (size_t)NELEM_W,
            Qh, Ql, Kh, Kl, Vh, Vl, nullptr);
    }
    // 2) causal flash attention -> context hi/lo
    {
        dim3 grid(SEQ / 128, BATCH * NHEAD);
        flash_mma<<<grid, 256, FH_BYTES>>>(Qh, Ql, Kh, Kl, Vh, Vl, Ch, Cl);
    }
    // 3) output projection -> fp32 out
    {
        dim3 grid(EMB / BN, MTOT / BM, 1);
        gemm_hl<0><<<grid, 256, GSM>>>(
            Ch, Cl,
            Wh + 3 * (size_t)NELEM_W, Wl + 3 * (size_t)NELEM_W,
            nullptr, nullptr, nullptr, nullptr,
            nullptr, nullptr, nullptr, nullptr, nullptr, nullptr, out);
    }
}

// round 8
// speedup vs baseline: 1.4407x; 1.3908x over previous
#include <cuda_runtime.h>
#include <cuda_fp16.h>
#include <math.h>
#include <stdint.h>

#define BATCH  4
#define SEQ    2048
#define EMB    2048
#define NHEAD  16
#define HDIM   128
#define MTOT   (BATCH*SEQ)      // 8192
#define KDIM   2048
#define NELEM_X (MTOT*KDIM)     // 16.8M
#define NELEM_W (KDIM*KDIM)     // 4.19M

// ---------------- scratch (device globals: allocation-free rule) ----------------
__device__ __half g_xh[NELEM_X];
__device__ __half g_Wh[4][NELEM_W], g_Wl[4][NELEM_W];
__device__ __half g_Qh[NELEM_X], g_Ql[NELEM_X];
__device__ __half g_Kh[NELEM_X], g_Kl[NELEM_X];
__device__ __half g_Vh[NELEM_X], g_Vl[NELEM_X];
__device__ __half g_Ch[NELEM_X];

__device__ __forceinline__ uint32_t smem_u32(const void* p) {
    uint32_t a;
    asm("{ .reg .u64 t; cvta.to.shared.u64 t, %1; cvt.u32.u64 %0, t; }" : "=r"(a) : "l"(p));
    return a;
}

#define CP_ASYNC16(dst, src) \
    asm volatile("cp.async.cg.shared.global [%0], [%1], 16;" :: "r"(dst), "l"(src))
#define CP_COMMIT() asm volatile("cp.async.commit_group;" ::: "memory")
#define CP_WAIT(n)  asm volatile("cp.async.wait_group %0;" :: "n"(n) : "memory")

#define LDMX4(r0,r1,r2,r3, addr) \
    asm volatile("ldmatrix.sync.aligned.m8n8.x4.shared.b16 {%0,%1,%2,%3}, [%4];" \
        : "=r"(r0),"=r"(r1),"=r"(r2),"=r"(r3) : "r"(addr))
#define LDMX4T(r0,r1,r2,r3, addr) \
    asm volatile("ldmatrix.sync.aligned.m8n8.x4.trans.shared.b16 {%0,%1,%2,%3}, [%4];" \
        : "=r"(r0),"=r"(r1),"=r"(r2),"=r"(r3) : "r"(addr))

#define MMA16816(c, a0,a1,a2,a3, b0,b1) \
    asm volatile("mma.sync.aligned.m16n8k16.row.col.f32.f16.f16.f32 " \
        "{%0,%1,%2,%3}, {%4,%5,%6,%7}, {%8,%9}, {%0,%1,%2,%3};" \
        : "+f"((c)[0]),"+f"((c)[1]),"+f"((c)[2]),"+f"((c)[3]) \
        : "r"(a0),"r"(a1),"r"(a2),"r"(a3), "r"(b0),"r"(b1))

__device__ __forceinline__ uint32_t pack_h2(__half x, __half y) {
    __half2 h = __halves2half2(x, y);
    return *(uint32_t*)&h;
}
__device__ __forceinline__ void split_hl(float x, float y, uint32_t& hp, uint32_t& lp) {
    __half hx = __float2half_rn(x), hy = __float2half_rn(y);
    hp = pack_h2(hx, hy);
    lp = pack_h2(__float2half_rn(x - __half2float(hx)),
                 __float2half_rn(y - __half2float(hy)));
}

// =================================================================================
// fused pre-convert: x -> hi only; Wq/Wk/Wv/Wo -> hi + lo.
// =================================================================================
#define XB (NELEM_X/2048)
#define WB (NELEM_W/2048)

__global__ void __launch_bounds__(256) conv_all(
    const float* __restrict__ x,
    const float* __restrict__ Wq, const float* __restrict__ Wk,
    const float* __restrict__ Wv, const float* __restrict__ Wo,
    __half* __restrict__ xh,
    __half* __restrict__ Wh, __half* __restrict__ Wl)
{
    int blk = blockIdx.x;
    if (blk < XB) {
        int i0 = blk * 512 + threadIdx.x;
        #pragma unroll
        for (int k = 0; k < 2; k++) {
            int i = i0 + k * 256;
            float4 v = ((const float4*)x)[i];
            uint2 hp;
            hp.x = pack_h2(__float2half_rn(v.x), __float2half_rn(v.y));
            hp.y = pack_h2(__float2half_rn(v.z), __float2half_rn(v.w));
            ((uint2*)xh)[i] = hp;
        }
    } else {
        int wi = (blk - XB) / WB;
        blk = (blk - XB) % WB;
        const float* s = (wi == 0) ? Wq : (wi == 1) ? Wk : (wi == 2) ? Wv : Wo;
        __half* h = Wh + (size_t)wi * NELEM_W;
        __half* l = Wl + (size_t)wi * NELEM_W;
        int i0 = blk * 512 + threadIdx.x;
        #pragma unroll
        for (int k = 0; k < 2; k++) {
            int i = i0 + k * 256;
            float4 v = ((const float4*)s)[i];
            uint2 hp, lp;
            split_hl(v.x, v.y, hp.x, lp.x);
            split_hl(v.z, v.w, hp.y, lp.y);
            ((uint2*)h)[i] = hp;
            ((uint2*)l)[i] = lp;
        }
    }
}

// =================================================================================
// 2-pass mma GEMM: C[m,n] = sum_k Ah[m,k]*(Wh+Wl)[n,k]
// BM=128, BN=64, BK=64; 8 warps 2x4; 3-stage cp.async ring; ONE sync/stage;
// 32KB/stage -> 96KB total -> 2 CTAs/SM.
// MODE 0: plain fp32 store.  MODE 1: QKV (z), RoPE for z<2, hi/lo fp16 [B,H,S,D].
// =================================================================================
#define BM 128
#define BN 64
#define BK 64
#define NSTG (KDIM/BK)     // 32

#define GS_AH 0
#define GS_BH 16384
#define GS_BL 24576
#define GS_STRIDE 32768
#define GSM (3*GS_STRIDE)   // 96KB

template<int MODE>
__global__ void __launch_bounds__(256, 2) gemm_hl(
    const __half* __restrict__ Ah,
    const __half* __restrict__ Bh0, const __half* __restrict__ Bl0,
    const __half* __restrict__ Bh1, const __half* __restrict__ Bl1,
    const __half* __restrict__ Bh2, const __half* __restrict__ Bl2,
    __half* __restrict__ Dh0, __half* __restrict__ Dl0,
    __half* __restrict__ Dh1, __half* __restrict__ Dl1,
    __half* __restrict__ Dh2, __half* __restrict__ Dl2,
    float* __restrict__ Dout)
{
    extern __shared__ char sm[];
    const uint32_t sb = smem_u32(sm);

    const __half* Bh = Bh0;
    const __half* Bl = Bl0;
    int z = 0;
    if (MODE == 1) {
        z = blockIdx.z;
        if (z == 1) { Bh = Bh1; Bl = Bl1; }
        else if (z == 2) { Bh = Bh2; Bl = Bl2; }
    }

    const int tid = threadIdx.x;
    const int wid = tid >> 5;
    const int lid = tid & 31;
    const int wm = wid >> 2;
    const int wn = wid & 3;
    const int m0 = blockIdx.y * BM;
    const int n0 = blockIdx.x * BN;

    float acc[4][2][4];
    #pragma unroll
    for (int i = 0; i < 4; i++)
        #pragma unroll
        for (int j = 0; j < 2; j++)
            #pragma unroll
            for (int k = 0; k < 4; k++) acc[i][j][k] = 0.f;

    // 8 cp.async chunks / thread / stage: A hi 1024, B hi 512, B lo 512
    auto issue_stage = [&](int s) {
        const int kt = s * BK;
        const uint32_t base = sb + (uint32_t)(s % 3) * GS_STRIDE;
        #pragma unroll
        for (int i = 0; i < 4; i++) {
            int c = i * 256 + tid;
            int r = c >> 3, c16 = c & 7;
            uint32_t off = (uint32_t)(r * 128 + c16 * 16);
            off ^= (off >> 3) & 0x70;
            CP_ASYNC16(base + GS_AH + off, Ah + (size_t)(m0 + r) * KDIM + kt + c16 * 8);
        }
        #pragma unroll
        for (int i = 0; i < 2; i++) {
            int c = i * 256 + tid;
            int r = c >> 3, c16 = c & 7;
            uint32_t off = (uint32_t)(r * 128 + c16 * 16);
            off ^= (off >> 3) & 0x70;
            const size_t gb = (size_t)(n0 + r) * KDIM + kt + c16 * 8;
            CP_ASYNC16(base + GS_BH + off, Bh + gb);
            CP_ASYNC16(base + GS_BL + off, Bl + gb);
        }
        CP_COMMIT();
    };

    auto compute_stage = [&](int s) {
        const uint32_t base = sb + (uint32_t)(s % 3) * GS_STRIDE;
        const int lr = lid & 15;
        const int lc = lid >> 4;
        #pragma unroll
        for (int ks = 0; ks < 4; ks++) {
            uint32_t boff = (uint32_t)((wn * 16 + lr) * 128 + ks * 32 + lc * 16);
            boff ^= (boff >> 3) & 0x70;
            uint32_t bh0, bh1, bh2, bh3, bl0, bl1, bl2, bl3;
            LDMX4(bh0, bh1, bh2, bh3, base + GS_BH + boff);
            LDMX4(bl0, bl1, bl2, bl3, base + GS_BL + boff);
            #pragma unroll
            for (int mt = 0; mt < 4; mt++) {
                uint32_t aoff = (uint32_t)((wm * 64 + mt * 16 + lr) * 128 + ks * 32 + lc * 16);
                aoff ^= (aoff >> 3) & 0x70;
                uint32_t a0, a1, a2, a3;
                LDMX4(a0, a1, a2, a3, base + GS_AH + aoff);
                MMA16816(acc[mt][0], a0, a1, a2, a3, bh0, bh2);
                MMA16816(acc[mt][0], a0, a1, a2, a3, bl0, bl2);
                MMA16816(acc[mt][1], a0, a1, a2, a3, bh1, bh3);
                MMA16816(acc[mt][1], a0, a1, a2, a3, bl1, bl3);
            }
        }
    };

    issue_stage(0);
    issue_stage(1);
    for (int s = 0; s < NSTG; s++) {
        if (s + 1 < NSTG) CP_WAIT(1); else CP_WAIT(0);
        __syncthreads();            // stage s visible; all warps past compute(s-1)
        compute_stage(s);
        if (s + 2 < NSTG) issue_stage(s + 2);
    }

    // ---------------- epilogue ----------------
    const int rrow = lid >> 2;
    const int cpair = (lid & 3) * 2;
    #pragma unroll
    for (int mt = 0; mt < 4; mt++) {
        #pragma unroll
        for (int nt = 0; nt < 2; nt++) {
            int n = n0 + wn * 16 + nt * 8 + cpair;
            if (MODE == 0) {
                #pragma unroll
                for (int hf = 0; hf < 2; hf++) {
                    int m = m0 + wm * 64 + mt * 16 + rrow + hf * 8;
                    *(float2*)(Dout + (size_t)m * EMB + n) =
                        make_float2(acc[mt][nt][2 * hf], acc[mt][nt][2 * hf + 1]);
                }
            } else {
                __half* Dh = (z == 0) ? Dh0 : (z == 1) ? Dh1 : Dh2;
                __half* Dl = (z == 0) ? Dl0 : (z == 1) ? Dl1 : Dl2;
                int h  = n >> 7;
                int dd = n & 127;
                float invf = powf(10000.0f, -(float)(dd >> 1) * (1.0f / 64.0f));
                #pragma unroll
                for (int hf = 0; hf < 2; hf++) {
                    int m = m0 + wm * 64 + mt * 16 + rrow + hf * 8;
                    int bb = m >> 11;
                    int sq = m & 2047;
                    float c0 = acc[mt][nt][2 * hf], c1 = acc[mt][nt][2 * hf + 1];
                    float v0 = c0, v1 = c1;
                    if (z < 2) {
                        float ang = (float)sq * invf;
                        float sn, cs;
                        sincosf(ang, &sn, &cs);
                        v0 = c0 * cs - c1 * sn;
                        v1 = c1 * cs + c0 * sn;
                    }
                    size_t idx = ((size_t)(bb * NHEAD + h) * SEQ + sq) * HDIM + dd;
                    uint32_t hp, lp;
                    split_hl(v0, v1, hp, lp);
                    *(uint32_t*)(Dh + idx) = hp;
                    *(uint32_t*)(Dl + idx) = lp;
                }
            }
        }
    }
}

// =================================================================================
// Flash attention (R5 structure, 3-pass, K/V double-buffered); context hi only.
// =================================================================================
#define FQH 0
#define FQL 32768
#define FKV 65536
#define FKV_STRIDE 65536
#define FKH 0
#define FKL 16384
#define FVH 32768
#define FVL 49152
#define FH_BYTES 196608

__device__ __forceinline__ uint32_t sw256(uint32_t off) {
    return off ^ ((off >> 4) & 0x70);
}

__global__ void __launch_bounds__(256, 1) flash_mma(
    const __half* __restrict__ Qh, const __half* __restrict__ Ql,
    const __half* __restrict__ Kh, const __half* __restrict__ Kl,
    const __half* __restrict__ Vh, const __half* __restrict__ Vl,
    __half* __restrict__ Ch)
{
    extern __shared__ char sm[];
    const uint32_t sb = smem_u32(sm);

    const int tid = threadIdx.x;
    const int wid = tid >> 5;
    const int lid = tid & 31;
    const int q0 = (gridDim.x - 1 - blockIdx.x) * 128;
    const int b  = blockIdx.y >> 4, h = blockIdx.y & 15;
    const size_t bh = ((size_t)(b * NHEAD + h)) * SEQ * HDIM;

    const int nIter = (q0 >> 6) + 2;

    auto issue_kv = [&](int it, int buf) {
        const int j0 = it * 64;
        const uint32_t base = sb + FKV + buf * FKV_STRIDE;
        #pragma unroll
        for (int i = 0; i < 4; i++) {
            int c = i * 256 + tid;
            int r = c >> 4, c16 = c & 15;
            uint32_t off = sw256((uint32_t)(r * 256 + c16 * 16));
            size_t src = bh + (size_t)(j0 + r) * HDIM + c16 * 8;
            CP_ASYNC16(base + FKH + off, Kh + src);
            CP_ASYNC16(base + FKL + off, Kl + src);
            CP_ASYNC16(base + FVH + off, Vh + src);
            CP_ASYNC16(base + FVL + off, Vl + src);
        }
        CP_COMMIT();
    };

    {
        #pragma unroll
        for (int i = 0; i < 8; i++) {
            int c = i * 256 + tid;
            int r = c >> 4, c16 = c & 15;
            uint32_t off = sw256((uint32_t)(r * 256 + c16 * 16));
            size_t src = bh + (size_t)(q0 + r) * HDIM + c16 * 8;
            CP_ASYNC16(sb + FQH + off, Qh + src);
            CP_ASYNC16(sb + FQL + off, Ql + src);
        }
    }
    issue_kv(0, 0);

    float os[16][4];
    #pragma unroll
    for (int i = 0; i < 16; i++)
        #pragma unroll
        for (int j = 0; j < 4; j++) os[i][j] = 0.f;
    float mrow[2] = {-1e30f, -1e30f};
    float lrow[2] = {0.f, 0.f};
    const float scale = 0.08838834764831845f;

    const int lr = lid & 15;
    const int lc = lid >> 4;

    for (int it = 0; it < nIter; it++) {
        const int j0 = it * 64;
        const int buf = it & 1;
        const uint32_t kbase = sb + FKV + buf * FKV_STRIDE;

        if (it + 1 < nIter) {
            issue_kv(it + 1, buf ^ 1);
            CP_WAIT(1);
        } else {
            CP_WAIT(0);
        }
        __syncthreads();

        if (j0 < q0 + (wid + 1) * 16) {
            float sacc[8][4];
            #pragma unroll
            for (int i = 0; i < 8; i++)
                #pragma unroll
                for (int j = 0; j < 4; j++) sacc[i][j] = 0.f;

            #pragma unroll
            for (int ks = 0; ks < 8; ks++) {
                uint32_t aoff = sw256((uint32_t)((wid * 16 + lr) * 256 + ks * 32 + lc * 16));
                uint32_t qh0, qh1, qh2, qh3, ql0, ql1, ql2, ql3;
                LDMX4(qh0, qh1, qh2, qh3, sb + FQH + aoff);
                LDMX4(ql0, ql1, ql2, ql3, sb + FQL + aoff);
                #pragma unroll
                for (int bg = 0; bg < 4; bg++) {
                    uint32_t boff = sw256((uint32_t)((bg * 16 + lr) * 256 + ks * 32 + lc * 16));
                    uint32_t kh0, kh1, kh2, kh3, kl0, kl1, kl2, kl3;
                    LDMX4(kh0, kh1, kh2, kh3, kbase + FKH + boff);
                    LDMX4(kl0, kl1, kl2, kl3, kbase + FKL + boff);
                    MMA16816(sacc[bg * 2],     qh0, qh1, qh2, qh3, kh0, kh2);
                    MMA16816(sacc[bg * 2],     qh0, qh1, qh2, qh3, kl0, kl2);
                    MMA16816(sacc[bg * 2],     ql0, ql1, ql2, ql3, kh0, kh2);
                    MMA16816(sacc[bg * 2 + 1], qh0, qh1, qh2, qh3, kh1, kh3);
                    MMA16816(sacc[bg * 2 + 1], qh0, qh1, qh2, qh3, kl1, kl3);
                    MMA16816(sacc[bg * 2 + 1], ql0, ql1, ql2, ql3, kh1, kh3);
                }
            }

            const int r0g = q0 + wid * 16 + (lid >> 2);
            const int c0g = j0 + 2 * (lid & 3);
            #pragma unroll
            for (int nt = 0; nt < 8; nt++)
                #pragma unroll
                for (int c = 0; c < 4; c++) {
                    int rr = r0g + ((c >= 2) ? 8 : 0);
                    int cc = c0g + nt * 8 + (c & 1);
                    float v = sacc[nt][c] * scale;
                    if (cc > rr) v = -1e30f;
                    sacc[nt][c] = v;
                }

            float mx0 = -1e30f, mx1 = -1e30f;
            #pragma unroll
            for (int nt = 0; nt < 8; nt++) {
                mx0 = fmaxf(mx0, fmaxf(sacc[nt][0], sacc[nt][1]));
                mx1 = fmaxf(mx1, fmaxf(sacc[nt][2], sacc[nt][3]));
            }
            #pragma unroll
            for (int o = 1; o < 4; o <<= 1) {
                mx0 = fmaxf(mx0, __shfl_xor_sync(0xffffffffu, mx0, o));
                mx1 = fmaxf(mx1, __shfl_xor_sync(0xffffffffu, mx1, o));
            }
            float mn0 = fmaxf(mrow[0], mx0);
            float mn1 = fmaxf(mrow[1], mx1);
            float cr0 = __expf(mrow[0] - mn0);
            float cr1 = __expf(mrow[1] - mn1);
            float rs0 = 0.f, rs1 = 0.f;
            #pragma unroll
            for (int nt = 0; nt < 8; nt++) {
                float p0 = __expf(sacc[nt][0] - mn0);
                float p1 = __expf(sacc[nt][1] - mn0);
                float p2 = __expf(sacc[nt][2] - mn1);
                float p3 = __expf(sacc[nt][3] - mn1);
                sacc[nt][0] = p0; sacc[nt][1] = p1; sacc[nt][2] = p2; sacc[nt][3] = p3;
                rs0 += p0 + p1; rs1 += p2 + p3;
            }
            #pragma unroll
            for (int o = 1; o < 4; o <<= 1) {
                rs0 += __shfl_xor_sync(0xffffffffu, rs0, o);
                rs1 += __shfl_xor_sync(0xffffffffu, rs1, o);
            }
            lrow[0] = lrow[0] * cr0 + rs0;
            lrow[1] = lrow[1] * cr1 + rs1;
            mrow[0] = mn0; mrow[1] = mn1;
            #pragma unroll
            for (int nt = 0; nt < 16; nt++) {
                os[nt][0] *= cr0; os[nt][1] *= cr0;
                os[nt][2] *= cr1; os[nt][3] *= cr1;
            }

            #pragma unroll
            for (int kt = 0; kt < 4; kt++) {
                uint32_t ah[4], al[4];
                #pragma unroll
                for (int q = 0; q < 4; q++) {
                    int nt = 2 * kt + (q >> 1);
                    int cc = (q & 1) * 2;
                    split_hl(sacc[nt][cc], sacc[nt][cc + 1], ah[q], al[q]);
                }
                const int vrow = kt * 16 + (lid & 7) + ((lid >> 3) & 1) * 8;
                const int vnh  = (lid >> 4) * 8;
                #pragma unroll
                for (int bg2 = 0; bg2 < 8; bg2++) {
                    uint32_t voff = sw256((uint32_t)(vrow * 256 + (bg2 * 16 + vnh) * 2));
                    uint32_t vh0, vh1, vh2, vh3, vl0, vl1, vl2, vl3;
                    LDMX4T(vh0, vh1, vh2, vh3, kbase + FVH + voff);
                    LDMX4T(vl0, vl1, vl2, vl3, kbase + FVL + voff);
                    MMA16816(os[bg2 * 2],     ah[0], ah[1], ah[2], ah[3], vh0, vh1);
                    MMA16816(os[bg2 * 2],     ah[0], ah[1], ah[2], ah[3], vl0, vl1);
                    MMA16816(os[bg2 * 2],     al[0], al[1], al[2], al[3], vh0, vh1);
                    MMA16816(os[bg2 * 2 + 1], ah[0], ah[1], ah[2], ah[3], vh2, vh3);
                    MMA16816(os[bg2 * 2 + 1], ah[0], ah[1], ah[2], ah[3], vl2, vl3);
                    MMA16816(os[bg2 * 2 + 1], al[0], al[1], al[2], al[3], vh2, vh3);
                }
            }
        }
        __syncthreads();
    }

    // epilogue: context hi fp16 only
    const float inv0 = 1.0f / lrow[0];
    const float inv1 = 1.0f / lrow[1];
    const int row0 = q0 + wid * 16 + (lid >> 2);
    const int dbase = 2 * (lid & 3);
    #pragma unroll
    for (int nt = 0; nt < 16; nt++) {
        int d = nt * 8 + dbase;
        size_t i0 = ((size_t)(b * SEQ + row0))     * EMB + h * HDIM + d;
        size_t i1 = ((size_t)(b * SEQ + row0 + 8)) * EMB + h * HDIM + d;
        *(uint32_t*)(Ch + i0) = pack_h2(__float2half_rn(os[nt][0] * inv0),
                                        __float2half_rn(os[nt][1] * inv0));
        *(uint32_t*)(Ch + i1) = pack_h2(__float2half_rn(os[nt][2] * inv1),
                                        __float2half_rn(os[nt][3] * inv1));
    }
}

// =================================================================================
extern "C" void kernel_launch(void* const* d_in, const int* in_sizes, int n_in,
                              void* d_out, int out_size)
{
    const float* x  = (const float*)d_in[0];
    const float* Wq = (const float*)d_in[1];
    const float* Wk = (const float*)d_in[2];
    const float* Wv = (const float*)d_in[3];
    const float* Wo = (const float*)d_in[4];
    float* out = (float*)d_out;

    __half *xh, *Wh, *Wl, *Qh, *Ql, *Kh, *Kl, *Vh, *Vl, *Ch;
    cudaGetSymbolAddress((void**)&xh, g_xh);
    cudaGetSymbolAddress((void**)&Wh, g_Wh);
    cudaGetSymbolAddress((void**)&Wl, g_Wl);
    cudaGetSymbolAddress((void**)&Qh, g_Qh);
    cudaGetSymbolAddress((void**)&Ql, g_Ql);
    cudaGetSymbolAddress((void**)&Kh, g_Kh);
    cudaGetSymbolAddress((void**)&Kl, g_Kl);
    cudaGetSymbolAddress((void**)&Vh, g_Vh);
    cudaGetSymbolAddress((void**)&Vl, g_Vl);
    cudaGetSymbolAddress((void**)&Ch, g_Ch);

    cudaFuncSetAttribute(gemm_hl<1>, cudaFuncAttributeMaxDynamicSharedMemorySize, GSM);
    cudaFuncSetAttribute(gemm_hl<0>, cudaFuncAttributeMaxDynamicSharedMemorySize, GSM);
    cudaFuncSetAttribute(flash_mma, cudaFuncAttributeMaxDynamicSharedMemorySize, FH_BYTES);

    // 0) fused pre-convert
    conv_all<<<XB + 4 * WB, 256>>>(x, Wq, Wk, Wv, Wo, xh, Wh, Wl);

    // 1) QKV projection (2-pass) + RoPE -> hi/lo [B,H,S,D]
    {
        dim3 grid(EMB / BN, MTOT / BM, 3);
        gemm_hl<1><<<grid, 256, GSM>>>(
            xh,
            Wh + 0 * (size_t)NELEM_W, Wl + 0 * (size_t)NELEM_W,
            Wh + 1 * (size_t)NELEM_W, Wl + 1 * (size_t)NELEM_W,
            Wh + 2 * (size_t)NELEM_W, Wl + 2 * (size_t)NELEM_W,
            Qh, Ql, Kh, Kl, Vh, Vl, nullptr);
    }
    // 2) causal flash attention (3-pass) -> context hi
    {
        dim3 grid(SEQ / 128, BATCH * NHEAD);
        flash_mma<<<grid, 256, FH_BYTES>>>(Qh, Ql, Kh, Kl, Vh, Vl, Ch);
    }
    // 3) output projection (2-pass) -> fp32 out
    {
        dim3 grid(EMB / BN, MTOT / BM, 1);
        gemm_hl<0><<<grid, 256, GSM>>>(
            Ch,
            Wh + 3 * (size_t)NELEM_W, Wl + 3 * (size_t)NELEM_W,
            nullptr, nullptr, nullptr, nullptr,
            nullptr, nullptr, nullptr, nullptr, nullptr, nullptr, out);
    }
}

// round 9
// speedup vs baseline: 1.5673x; 1.0879x over previous
#include <cuda_runtime.h>
#include <cuda_fp16.h>
#include <math.h>
#include <stdint.h>

#define BATCH  4
#define SEQ    2048
#define EMB    2048
#define NHEAD  16
#define HDIM   128
#define MTOT   (BATCH*SEQ)      // 8192
#define KDIM   2048
#define NELEM_X (MTOT*KDIM)     // 16.8M
#define NELEM_W (KDIM*KDIM)     // 4.19M

// ---------------- scratch (device globals: allocation-free rule) ----------------
__device__ __half g_xh[NELEM_X];
__device__ __half g_Wh[4][NELEM_W], g_Wl[4][NELEM_W];
__device__ __half g_Qh[NELEM_X];
__device__ __half g_Kh[NELEM_X], g_Kl[NELEM_X];
__device__ __half g_Vh[NELEM_X];
__device__ __half g_Ch[NELEM_X];

__device__ __forceinline__ uint32_t smem_u32(const void* p) {
    uint32_t a;
    asm("{ .reg .u64 t; cvta.to.shared.u64 t, %1; cvt.u32.u64 %0, t; }" : "=r"(a) : "l"(p));
    return a;
}

#define CP_ASYNC16(dst, src) \
    asm volatile("cp.async.cg.shared.global [%0], [%1], 16;" :: "r"(dst), "l"(src))
#define CP_COMMIT() asm volatile("cp.async.commit_group;" ::: "memory")
#define CP_WAIT(n)  asm volatile("cp.async.wait_group %0;" :: "n"(n) : "memory")

#define LDMX4(r0,r1,r2,r3, addr) \
    asm volatile("ldmatrix.sync.aligned.m8n8.x4.shared.b16 {%0,%1,%2,%3}, [%4];" \
        : "=r"(r0),"=r"(r1),"=r"(r2),"=r"(r3) : "r"(addr))
#define LDMX4T(r0,r1,r2,r3, addr) \
    asm volatile("ldmatrix.sync.aligned.m8n8.x4.trans.shared.b16 {%0,%1,%2,%3}, [%4];" \
        : "=r"(r0),"=r"(r1),"=r"(r2),"=r"(r3) : "r"(addr))

#define MMA16816(c, a0,a1,a2,a3, b0,b1) \
    asm volatile("mma.sync.aligned.m16n8k16.row.col.f32.f16.f16.f32 " \
        "{%0,%1,%2,%3}, {%4,%5,%6,%7}, {%8,%9}, {%0,%1,%2,%3};" \
        : "+f"((c)[0]),"+f"((c)[1]),"+f"((c)[2]),"+f"((c)[3]) \
        : "r"(a0),"r"(a1),"r"(a2),"r"(a3), "r"(b0),"r"(b1))

__device__ __forceinline__ uint32_t pack_h2(__half x, __half y) {
    __half2 h = __halves2half2(x, y);
    return *(uint32_t*)&h;
}
__device__ __forceinline__ void split_hl(float x, float y, uint32_t& hp, uint32_t& lp) {
    __half hx = __float2half_rn(x), hy = __float2half_rn(y);
    hp = pack_h2(hx, hy);
    lp = pack_h2(__float2half_rn(x - __half2float(hx)),
                 __float2half_rn(y - __half2float(hy)));
}

// =================================================================================
// fused pre-convert: x -> hi only; Wq/Wk/Wv/Wo -> hi + lo.
// =================================================================================
#define XB (NELEM_X/2048)
#define WB (NELEM_W/2048)

__global__ void __launch_bounds__(256) conv_all(
    const float* __restrict__ x,
    const float* __restrict__ Wq, const float* __restrict__ Wk,
    const float* __restrict__ Wv, const float* __restrict__ Wo,
    __half* __restrict__ xh,
    __half* __restrict__ Wh, __half* __restrict__ Wl)
{
    int blk = blockIdx.x;
    if (blk < XB) {
        int i0 = blk * 512 + threadIdx.x;
        #pragma unroll
        for (int k = 0; k < 2; k++) {
            int i = i0 + k * 256;
            float4 v = ((const float4*)x)[i];
            uint2 hp;
            hp.x = pack_h2(__float2half_rn(v.x), __float2half_rn(v.y));
            hp.y = pack_h2(__float2half_rn(v.z), __float2half_rn(v.w));
            ((uint2*)xh)[i] = hp;
        }
    } else {
        int wi = (blk - XB) / WB;
        blk = (blk - XB) % WB;
        const float* s = (wi == 0) ? Wq : (wi == 1) ? Wk : (wi == 2) ? Wv : Wo;
        __half* h = Wh + (size_t)wi * NELEM_W;
        __half* l = Wl + (size_t)wi * NELEM_W;
        int i0 = blk * 512 + threadIdx.x;
        #pragma unroll
        for (int k = 0; k < 2; k++) {
            int i = i0 + k * 256;
            float4 v = ((const float4*)s)[i];
            uint2 hp, lp;
            split_hl(v.x, v.y, hp.x, lp.x);
            split_hl(v.z, v.w, hp.y, lp.y);
            ((uint2*)h)[i] = hp;
            ((uint2*)l)[i] = lp;
        }
    }
}

// =================================================================================
// 2-pass mma GEMM: C[m,n] = sum_k Ah[m,k]*(Wh+Wl)[n,k]   (unchanged from R8)
// MODE 1 epilogue: Q (z=0) and V (z=2) store hi only; K (z=1) stores hi+lo.
// =================================================================================
#define BM 128
#define BN 64
#define BK 64
#define NSTG (KDIM/BK)     // 32

#define GS_AH 0
#define GS_BH 16384
#define GS_BL 24576
#define GS_STRIDE 32768
#define GSM (3*GS_STRIDE)   // 96KB

template<int MODE>
__global__ void __launch_bounds__(256, 2) gemm_hl(
    const __half* __restrict__ Ah,
    const __half* __restrict__ Bh0, const __half* __restrict__ Bl0,
    const __half* __restrict__ Bh1, const __half* __restrict__ Bl1,
    const __half* __restrict__ Bh2, const __half* __restrict__ Bl2,
    __half* __restrict__ Dh0,
    __half* __restrict__ Dh1, __half* __restrict__ Dl1,
    __half* __restrict__ Dh2,
    float* __restrict__ Dout)
{
    extern __shared__ char sm[];
    const uint32_t sb = smem_u32(sm);

    const __half* Bh = Bh0;
    const __half* Bl = Bl0;
    int z = 0;
    if (MODE == 1) {
        z = blockIdx.z;
        if (z == 1) { Bh = Bh1; Bl = Bl1; }
        else if (z == 2) { Bh = Bh2; Bl = Bl2; }
    }

    const int tid = threadIdx.x;
    const int wid = tid >> 5;
    const int lid = tid & 31;
    const int wm = wid >> 2;
    const int wn = wid & 3;
    const int m0 = blockIdx.y * BM;
    const int n0 = blockIdx.x * BN;

    float acc[4][2][4];
    #pragma unroll
    for (int i = 0; i < 4; i++)
        #pragma unroll
        for (int j = 0; j < 2; j++)
            #pragma unroll
            for (int k = 0; k < 4; k++) acc[i][j][k] = 0.f;

    auto issue_stage = [&](int s) {
        const int kt = s * BK;
        const uint32_t base = sb + (uint32_t)(s % 3) * GS_STRIDE;
        #pragma unroll
        for (int i = 0; i < 4; i++) {
            int c = i * 256 + tid;
            int r = c >> 3, c16 = c & 7;
            uint32_t off = (uint32_t)(r * 128 + c16 * 16);
            off ^= (off >> 3) & 0x70;
            CP_ASYNC16(base + GS_AH + off, Ah + (size_t)(m0 + r) * KDIM + kt + c16 * 8);
        }
        #pragma unroll
        for (int i = 0; i < 2; i++) {
            int c = i * 256 + tid;
            int r = c >> 3, c16 = c & 7;
            uint32_t off = (uint32_t)(r * 128 + c16 * 16);
            off ^= (off >> 3) & 0x70;
            const size_t gb = (size_t)(n0 + r) * KDIM + kt + c16 * 8;
            CP_ASYNC16(base + GS_BH + off, Bh + gb);
            CP_ASYNC16(base + GS_BL + off, Bl + gb);
        }
        CP_COMMIT();
    };

    auto compute_stage = [&](int s) {
        const uint32_t base = sb + (uint32_t)(s % 3) * GS_STRIDE;
        const int lr = lid & 15;
        const int lc = lid >> 4;
        #pragma unroll
        for (int ks = 0; ks < 4; ks++) {
            uint32_t boff = (uint32_t)((wn * 16 + lr) * 128 + ks * 32 + lc * 16);
            boff ^= (boff >> 3) & 0x70;
            uint32_t bh0, bh1, bh2, bh3, bl0, bl1, bl2, bl3;
            LDMX4(bh0, bh1, bh2, bh3, base + GS_BH + boff);
            LDMX4(bl0, bl1, bl2, bl3, base + GS_BL + boff);
            #pragma unroll
            for (int mt = 0; mt < 4; mt++) {
                uint32_t aoff = (uint32_t)((wm * 64 + mt * 16 + lr) * 128 + ks * 32 + lc * 16);
                aoff ^= (aoff >> 3) & 0x70;
                uint32_t a0, a1, a2, a3;
                LDMX4(a0, a1, a2, a3, base + GS_AH + aoff);
                MMA16816(acc[mt][0], a0, a1, a2, a3, bh0, bh2);
                MMA16816(acc[mt][0], a0, a1, a2, a3, bl0, bl2);
                MMA16816(acc[mt][1], a0, a1, a2, a3, bh1, bh3);
                MMA16816(acc[mt][1], a0, a1, a2, a3, bl1, bl3);
            }
        }
    };

    issue_stage(0);
    issue_stage(1);
    for (int s = 0; s < NSTG; s++) {
        if (s + 1 < NSTG) CP_WAIT(1); else CP_WAIT(0);
        __syncthreads();
        compute_stage(s);
        if (s + 2 < NSTG) issue_stage(s + 2);
    }

    // ---------------- epilogue ----------------
    const int rrow = lid >> 2;
    const int cpair = (lid & 3) * 2;
    #pragma unroll
    for (int mt = 0; mt < 4; mt++) {
        #pragma unroll
        for (int nt = 0; nt < 2; nt++) {
            int n = n0 + wn * 16 + nt * 8 + cpair;
            if (MODE == 0) {
                #pragma unroll
                for (int hf = 0; hf < 2; hf++) {
                    int m = m0 + wm * 64 + mt * 16 + rrow + hf * 8;
                    *(float2*)(Dout + (size_t)m * EMB + n) =
                        make_float2(acc[mt][nt][2 * hf], acc[mt][nt][2 * hf + 1]);
                }
            } else {
                __half* Dh = (z == 0) ? Dh0 : (z == 1) ? Dh1 : Dh2;
                int h  = n >> 7;
                int dd = n & 127;
                float invf = powf(10000.0f, -(float)(dd >> 1) * (1.0f / 64.0f));
                #pragma unroll
                for (int hf = 0; hf < 2; hf++) {
                    int m = m0 + wm * 64 + mt * 16 + rrow + hf * 8;
                    int bb = m >> 11;
                    int sq = m & 2047;
                    float c0 = acc[mt][nt][2 * hf], c1 = acc[mt][nt][2 * hf + 1];
                    float v0 = c0, v1 = c1;
                    if (z < 2) {
                        float ang = (float)sq * invf;
                        float sn, cs;
                        sincosf(ang, &sn, &cs);
                        v0 = c0 * cs - c1 * sn;
                        v1 = c1 * cs + c0 * sn;
                    }
                    size_t idx = ((size_t)(bb * NHEAD + h) * SEQ + sq) * HDIM + dd;
                    uint32_t hp, lp;
                    split_hl(v0, v1, hp, lp);
                    *(uint32_t*)(Dh + idx) = hp;
                    if (z == 1) *(uint32_t*)(Dl1 + idx) = lp;   // only K keeps residual
                }
            }
        }
    }
}

// =================================================================================
// Flash attention, asymmetric 2-pass:
//   S = Qh·(Kh + Kl)      (Q hi-only; K keeps residual)
//   O = (Ph + Pl)·Vh      (P residual in registers; V hi-only)
// smem: Qh 32K | 2 x (Kh 16K | Kl 16K | Vh 16K) = 128KB
// =================================================================================
#define FQH 0
#define FKV 32768
#define FKV_STRIDE 49152
#define FKH 0
#define FKL 16384
#define FVH 32768
#define FH_BYTES 131072

__device__ __forceinline__ uint32_t sw256(uint32_t off) {
    return off ^ ((off >> 4) & 0x70);
}

__global__ void __launch_bounds__(256, 1) flash_mma(
    const __half* __restrict__ Qh,
    const __half* __restrict__ Kh, const __half* __restrict__ Kl,
    const __half* __restrict__ Vh,
    __half* __restrict__ Ch)
{
    extern __shared__ char sm[];
    const uint32_t sb = smem_u32(sm);

    const int tid = threadIdx.x;
    const int wid = tid >> 5;
    const int lid = tid & 31;
    const int q0 = (gridDim.x - 1 - blockIdx.x) * 128;   // longest first
    const int b  = blockIdx.y >> 4, h = blockIdx.y & 15;
    const size_t bh = ((size_t)(b * NHEAD + h)) * SEQ * HDIM;

    const int nIter = (q0 >> 6) + 2;

    auto issue_kv = [&](int it, int buf) {
        const int j0 = it * 64;
        const uint32_t base = sb + FKV + buf * FKV_STRIDE;
        #pragma unroll
        for (int i = 0; i < 4; i++) {
            int c = i * 256 + tid;
            int r = c >> 4, c16 = c & 15;
            uint32_t off = sw256((uint32_t)(r * 256 + c16 * 16));
            size_t src = bh + (size_t)(j0 + r) * HDIM + c16 * 8;
            CP_ASYNC16(base + FKH + off, Kh + src);
            CP_ASYNC16(base + FKL + off, Kl + src);
            CP_ASYNC16(base + FVH + off, Vh + src);
        }
        CP_COMMIT();
    };

    {   // Q hi: 2048 16B chunks
        #pragma unroll
        for (int i = 0; i < 8; i++) {
            int c = i * 256 + tid;
            int r = c >> 4, c16 = c & 15;
            uint32_t off = sw256((uint32_t)(r * 256 + c16 * 16));
            CP_ASYNC16(sb + FQH + off, Qh + bh + (size_t)(q0 + r) * HDIM + c16 * 8);
        }
    }
    issue_kv(0, 0);

    float os[16][4];
    #pragma unroll
    for (int i = 0; i < 16; i++)
        #pragma unroll
        for (int j = 0; j < 4; j++) os[i][j] = 0.f;
    float mrow[2] = {-1e30f, -1e30f};
    float lrow[2] = {0.f, 0.f};
    const float scale = 0.08838834764831845f;

    const int lr = lid & 15;
    const int lc = lid >> 4;

    for (int it = 0; it < nIter; it++) {
        const int j0 = it * 64;
        const int buf = it & 1;
        const uint32_t kbase = sb + FKV + buf * FKV_STRIDE;

        if (it + 1 < nIter) {
            issue_kv(it + 1, buf ^ 1);
            CP_WAIT(1);
        } else {
            CP_WAIT(0);
        }
        __syncthreads();

        if (j0 < q0 + (wid + 1) * 16) {
            float sacc[8][4];
            #pragma unroll
            for (int i = 0; i < 8; i++)
                #pragma unroll
                for (int j = 0; j < 4; j++) sacc[i][j] = 0.f;

            // ---- S = Qh (Kh + Kl) ----
            #pragma unroll
            for (int ks = 0; ks < 8; ks++) {
                uint32_t aoff = sw256((uint32_t)((wid * 16 + lr) * 256 + ks * 32 + lc * 16));
                uint32_t qh0, qh1, qh2, qh3;
                LDMX4(qh0, qh1, qh2, qh3, sb + FQH + aoff);
                #pragma unroll
                for (int bg = 0; bg < 4; bg++) {
                    uint32_t boff = sw256((uint32_t)((bg * 16 + lr) * 256 + ks * 32 + lc * 16));
                    uint32_t kh0, kh1, kh2, kh3, kl0, kl1, kl2, kl3;
                    LDMX4(kh0, kh1, kh2, kh3, kbase + FKH + boff);
                    LDMX4(kl0, kl1, kl2, kl3, kbase + FKL + boff);
                    MMA16816(sacc[bg * 2],     qh0, qh1, qh2, qh3, kh0, kh2);
                    MMA16816(sacc[bg * 2],     qh0, qh1, qh2, qh3, kl0, kl2);
                    MMA16816(sacc[bg * 2 + 1], qh0, qh1, qh2, qh3, kh1, kh3);
                    MMA16816(sacc[bg * 2 + 1], qh0, qh1, qh2, qh3, kl1, kl3);
                }
            }

            const int r0g = q0 + wid * 16 + (lid >> 2);
            const int c0g = j0 + 2 * (lid & 3);
            #pragma unroll
            for (int nt = 0; nt < 8; nt++)
                #pragma unroll
                for (int c = 0; c < 4; c++) {
                    int rr = r0g + ((c >= 2) ? 8 : 0);
                    int cc = c0g + nt * 8 + (c & 1);
                    float v = sacc[nt][c] * scale;
                    if (cc > rr) v = -1e30f;
                    sacc[nt][c] = v;
                }

            float mx0 = -1e30f, mx1 = -1e30f;
            #pragma unroll
            for (int nt = 0; nt < 8; nt++) {
                mx0 = fmaxf(mx0, fmaxf(sacc[nt][0], sacc[nt][1]));
                mx1 = fmaxf(mx1, fmaxf(sacc[nt][2], sacc[nt][3]));
            }
            #pragma unroll
            for (int o = 1; o < 4; o <<= 1) {
                mx0 = fmaxf(mx0, __shfl_xor_sync(0xffffffffu, mx0, o));
                mx1 = fmaxf(mx1, __shfl_xor_sync(0xffffffffu, mx1, o));
            }
            float mn0 = fmaxf(mrow[0], mx0);
            float mn1 = fmaxf(mrow[1], mx1);
            float cr0 = __expf(mrow[0] - mn0);
            float cr1 = __expf(mrow[1] - mn1);
            float rs0 = 0.f, rs1 = 0.f;
            #pragma unroll
            for (int nt = 0; nt < 8; nt++) {
                float p0 = __expf(sacc[nt][0] - mn0);
                float p1 = __expf(sacc[nt][1] - mn0);
                float p2 = __expf(sacc[nt][2] - mn1);
                float p3 = __expf(sacc[nt][3] - mn1);
                sacc[nt][0] = p0; sacc[nt][1] = p1; sacc[nt][2] = p2; sacc[nt][3] = p3;
                rs0 += p0 + p1; rs1 += p2 + p3;
            }
            #pragma unroll
            for (int o = 1; o < 4; o <<= 1) {
                rs0 += __shfl_xor_sync(0xffffffffu, rs0, o);
                rs1 += __shfl_xor_sync(0xffffffffu, rs1, o);
            }
            lrow[0] = lrow[0] * cr0 + rs0;
            lrow[1] = lrow[1] * cr1 + rs1;
            mrow[0] = mn0; mrow[1] = mn1;
            #pragma unroll
            for (int nt = 0; nt < 16; nt++) {
                os[nt][0] *= cr0; os[nt][1] *= cr0;
                os[nt][2] *= cr1; os[nt][3] *= cr1;
            }

            // ---- O += (Ph + Pl) Vh ----
            #pragma unroll
            for (int kt = 0; kt < 4; kt++) {
                uint32_t ah[4], al[4];
                #pragma unroll
                for (int q = 0; q < 4; q++) {
                    int nt = 2 * kt + (q >> 1);
                    int cc = (q & 1) * 2;
                    split_hl(sacc[nt][cc], sacc[nt][cc + 1], ah[q], al[q]);
                }
                const int vrow = kt * 16 + (lid & 7) + ((lid >> 3) & 1) * 8;
                const int vnh  = (lid >> 4) * 8;
                #pragma unroll
                for (int bg2 = 0; bg2 < 8; bg2++) {
                    uint32_t voff = sw256((uint32_t)(vrow * 256 + (bg2 * 16 + vnh) * 2));
                    uint32_t vh0, vh1, vh2, vh3;
                    LDMX4T(vh0, vh1, vh2, vh3, kbase + FVH + voff);
                    MMA16816(os[bg2 * 2],     ah[0], ah[1], ah[2], ah[3], vh0, vh1);
                    MMA16816(os[bg2 * 2],     al[0], al[1], al[2], al[3], vh0, vh1);
                    MMA16816(os[bg2 * 2 + 1], ah[0], ah[1], ah[2], ah[3], vh2, vh3);
                    MMA16816(os[bg2 * 2 + 1], al[0], al[1], al[2], al[3], vh2, vh3);
                }
            }
        }
        __syncthreads();
    }

    // epilogue: context hi fp16
    const float inv0 = 1.0f / lrow[0];
    const float inv1 = 1.0f / lrow[1];
    const int row0 = q0 + wid * 16 + (lid >> 2);
    const int dbase = 2 * (lid & 3);
    #pragma unroll
    for (int nt = 0; nt < 16; nt++) {
        int d = nt * 8 + dbase;
        size_t i0 = ((size_t)(b * SEQ + row0))     * EMB + h * HDIM + d;
        size_t i1 = ((size_t)(b * SEQ + row0 + 8)) * EMB + h * HDIM + d;
        *(uint32_t*)(Ch + i0) = pack_h2(__float2half_rn(os[nt][0] * inv0),
                                        __float2half_rn(os[nt][1] * inv0));
        *(uint32_t*)(Ch + i1) = pack_h2(__float2half_rn(os[nt][2] * inv1),
                                        __float2half_rn(os[nt][3] * inv1));
    }
}

// =================================================================================
extern "C" void kernel_launch(void* const* d_in, const int* in_sizes, int n_in,
                              void* d_out, int out_size)
{
    const float* x  = (const float*)d_in[0];
    const float* Wq = (const float*)d_in[1];
    const float* Wk = (const float*)d_in[2];
    const float* Wv = (const float*)d_in[3];
    const float* Wo = (const float*)d_in[4];
    float* out = (float*)d_out;

    __half *xh, *Wh, *Wl, *Qh, *Kh, *Kl, *Vh, *Ch;
    cudaGetSymbolAddress((void**)&xh, g_xh);
    cudaGetSymbolAddress((void**)&Wh, g_Wh);
    cudaGetSymbolAddress((void**)&Wl, g_Wl);
    cudaGetSymbolAddress((void**)&Qh, g_Qh);
    cudaGetSymbolAddress((void**)&Kh, g_Kh);
    cudaGetSymbolAddress((void**)&Kl, g_Kl);
    cudaGetSymbolAddress((void**)&Vh, g_Vh);
    cudaGetSymbolAddress((void**)&Ch, g_Ch);

    cudaFuncSetAttribute(gemm_hl<1>, cudaFuncAttributeMaxDynamicSharedMemorySize, GSM);
    cudaFuncSetAttribute(gemm_hl<0>, cudaFuncAttributeMaxDynamicSharedMemorySize, GSM);
    cudaFuncSetAttribute(flash_mma, cudaFuncAttributeMaxDynamicSharedMemorySize, FH_BYTES);

    // 0) fused pre-convert
    conv_all<<<XB + 4 * WB, 256>>>(x, Wq, Wk, Wv, Wo, xh, Wh, Wl);

    // 1) QKV projection (2-pass) + RoPE; Q,V hi-only; K hi+lo
    {
        dim3 grid(EMB / BN, MTOT / BM, 3);
        gemm_hl<1><<<grid, 256, GSM>>>(
            xh,
            Wh + 0 * (size_t)NELEM_W, Wl + 0 * (size_t)NELEM_W,
            Wh + 1 * (size_t)NELEM_W, Wl + 1 * (size_t)NELEM_W,
            Wh + 2 * (size_t)NELEM_W, Wl + 2 * (size_t)NELEM_W,
            Qh, Kh, Kl, Vh, nullptr);
    }
    // 2) causal flash attention (asymmetric 2-pass) -> context hi
    {
        dim3 grid(SEQ / 128, BATCH * NHEAD);
        flash_mma<<<grid, 256, FH_BYTES>>>(Qh, Kh, Kl, Vh, Ch);
    }
    // 3) output projection (2-pass) -> fp32 out
    {
        dim3 grid(EMB / BN, MTOT / BM, 1);
        gemm_hl<0><<<grid, 256, GSM>>>(
            Ch,
            Wh + 3 * (size_t)NELEM_W, Wl + 3 * (size_t)NELEM_W,
            nullptr, nullptr, nullptr, nullptr,
            nullptr, nullptr, nullptr, nullptr, out);
    }
}

// round 10
// speedup vs baseline: 2.1961x; 1.4012x over previous
#include <cuda_runtime.h>
#include <cuda_fp16.h>
#include <math.h>
#include <stdint.h>

#define BATCH  4
#define SEQ    2048
#define EMB    2048
#define NHEAD  16
#define HDIM   128
#define MTOT   (BATCH*SEQ)      // 8192
#define KDIM   2048
#define NELEM_X (MTOT*KDIM)     // 16.8M
#define NELEM_W (KDIM*KDIM)     // 4.19M

// ---------------- scratch (device globals: allocation-free rule) ----------------
__device__ __half g_xh[NELEM_X];
__device__ __half g_Wh[4][NELEM_W];
__device__ __half g_Qh[NELEM_X];
__device__ __half g_Kh[NELEM_X], g_Kl[NELEM_X];
__device__ __half g_Vh[NELEM_X];
__device__ __half g_Ch[NELEM_X];

__device__ __forceinline__ uint32_t smem_u32(const void* p) {
    uint32_t a;
    asm("{ .reg .u64 t; cvta.to.shared.u64 t, %1; cvt.u32.u64 %0, t; }" : "=r"(a) : "l"(p));
    return a;
}

#define CP_ASYNC16(dst, src) \
    asm volatile("cp.async.cg.shared.global [%0], [%1], 16;" :: "r"(dst), "l"(src))
#define CP_COMMIT() asm volatile("cp.async.commit_group;" ::: "memory")
#define CP_WAIT(n)  asm volatile("cp.async.wait_group %0;" :: "n"(n) : "memory")

#define LDMX4(r0,r1,r2,r3, addr) \
    asm volatile("ldmatrix.sync.aligned.m8n8.x4.shared.b16 {%0,%1,%2,%3}, [%4];" \
        : "=r"(r0),"=r"(r1),"=r"(r2),"=r"(r3) : "r"(addr))
#define LDMX4T(r0,r1,r2,r3, addr) \
    asm volatile("ldmatrix.sync.aligned.m8n8.x4.trans.shared.b16 {%0,%1,%2,%3}, [%4];" \
        : "=r"(r0),"=r"(r1),"=r"(r2),"=r"(r3) : "r"(addr))

#define MMA16816(c, a0,a1,a2,a3, b0,b1) \
    asm volatile("mma.sync.aligned.m16n8k16.row.col.f32.f16.f16.f32 " \
        "{%0,%1,%2,%3}, {%4,%5,%6,%7}, {%8,%9}, {%0,%1,%2,%3};" \
        : "+f"((c)[0]),"+f"((c)[1]),"+f"((c)[2]),"+f"((c)[3]) \
        : "r"(a0),"r"(a1),"r"(a2),"r"(a3), "r"(b0),"r"(b1))

__device__ __forceinline__ uint32_t pack_h2(__half x, __half y) {
    __half2 h = __halves2half2(x, y);
    return *(uint32_t*)&h;
}
__device__ __forceinline__ void split_hl(float x, float y, uint32_t& hp, uint32_t& lp) {
    __half hx = __float2half_rn(x), hy = __float2half_rn(y);
    hp = pack_h2(hx, hy);
    lp = pack_h2(__float2half_rn(x - __half2float(hx)),
                 __float2half_rn(y - __half2float(hy)));
}

// =================================================================================
// fused pre-convert: x and all W -> fp16 hi only.
// =================================================================================
#define XB (NELEM_X/2048)
#define WB (NELEM_W/2048)

__global__ void __launch_bounds__(256) conv_all(
    const float* __restrict__ x,
    const float* __restrict__ Wq, const float* __restrict__ Wk,
    const float* __restrict__ Wv, const float* __restrict__ Wo,
    __half* __restrict__ xh, __half* __restrict__ Wh)
{
    int blk = blockIdx.x;
    const float* s;
    __half* h;
    if (blk < XB) {
        s = x; h = xh;
    } else {
        int wi = (blk - XB) / WB;
        blk = (blk - XB) % WB;
        s = (wi == 0) ? Wq : (wi == 1) ? Wk : (wi == 2) ? Wv : Wo;
        h = Wh + (size_t)wi * NELEM_W;
    }
    int i0 = blk * 512 + threadIdx.x;
    #pragma unroll
    for (int k = 0; k < 2; k++) {
        int i = i0 + k * 256;
        float4 v = ((const float4*)s)[i];
        uint2 hp;
        hp.x = pack_h2(__float2half_rn(v.x), __float2half_rn(v.y));
        hp.y = pack_h2(__float2half_rn(v.z), __float2half_rn(v.w));
        ((uint2*)h)[i] = hp;
    }
}

// =================================================================================
// single-pass fp16 mma GEMM: C[m,n] = sum_k Ah[m,k]*Wh[n,k]
// BM=128, BN=64, BK=64; 8 warps 2x4; 3-stage cp.async ring; one sync/stage;
// 24KB/stage -> 72KB -> 2 CTAs/SM.
// MODE 0: fp32 store.  MODE 1: QKV (z), RoPE for z<2; Q,V hi; K hi+lo (of result).
// =================================================================================
#define BM 128
#define BN 64
#define BK 64
#define NSTG (KDIM/BK)     // 32

#define GS_AH 0
#define GS_BH 16384
#define GS_STRIDE 24576
#define GSM (3*GS_STRIDE)   // 72KB

template<int MODE>
__global__ void __launch_bounds__(256, 2) gemm_hl(
    const __half* __restrict__ Ah,
    const __half* __restrict__ Bh0, const __half* __restrict__ Bh1,
    const __half* __restrict__ Bh2,
    __half* __restrict__ Dh0,
    __half* __restrict__ Dh1, __half* __restrict__ Dl1,
    __half* __restrict__ Dh2,
    float* __restrict__ Dout)
{
    extern __shared__ char sm[];
    const uint32_t sb = smem_u32(sm);

    const __half* Bh = Bh0;
    int z = 0;
    if (MODE == 1) {
        z = blockIdx.z;
        if (z == 1) Bh = Bh1;
        else if (z == 2) Bh = Bh2;
    }

    const int tid = threadIdx.x;
    const int wid = tid >> 5;
    const int lid = tid & 31;
    const int wm = wid >> 2;
    const int wn = wid & 3;
    const int m0 = blockIdx.y * BM;
    const int n0 = blockIdx.x * BN;

    float acc[4][2][4];
    #pragma unroll
    for (int i = 0; i < 4; i++)
        #pragma unroll
        for (int j = 0; j < 2; j++)
            #pragma unroll
            for (int k = 0; k < 4; k++) acc[i][j][k] = 0.f;

    // 6 cp.async chunks / thread / stage: A 1024 chunks, B 512 chunks
    auto issue_stage = [&](int s) {
        const int kt = s * BK;
        const uint32_t base = sb + (uint32_t)(s % 3) * GS_STRIDE;
        #pragma unroll
        for (int i = 0; i < 4; i++) {
            int c = i * 256 + tid;
            int r = c >> 3, c16 = c & 7;
            uint32_t off = (uint32_t)(r * 128 + c16 * 16);
            off ^= (off >> 3) & 0x70;
            CP_ASYNC16(base + GS_AH + off, Ah + (size_t)(m0 + r) * KDIM + kt + c16 * 8);
        }
        #pragma unroll
        for (int i = 0; i < 2; i++) {
            int c = i * 256 + tid;
            int r = c >> 3, c16 = c & 7;
            uint32_t off = (uint32_t)(r * 128 + c16 * 16);
            off ^= (off >> 3) & 0x70;
            CP_ASYNC16(base + GS_BH + off, Bh + (size_t)(n0 + r) * KDIM + kt + c16 * 8);
        }
        CP_COMMIT();
    };

    auto compute_stage = [&](int s) {
        const uint32_t base = sb + (uint32_t)(s % 3) * GS_STRIDE;
        const int lr = lid & 15;
        const int lc = lid >> 4;
        #pragma unroll
        for (int ks = 0; ks < 4; ks++) {
            uint32_t boff = (uint32_t)((wn * 16 + lr) * 128 + ks * 32 + lc * 16);
            boff ^= (boff >> 3) & 0x70;
            uint32_t bh0, bh1, bh2, bh3;
            LDMX4(bh0, bh1, bh2, bh3, base + GS_BH + boff);
            #pragma unroll
            for (int mt = 0; mt < 4; mt++) {
                uint32_t aoff = (uint32_t)((wm * 64 + mt * 16 + lr) * 128 + ks * 32 + lc * 16);
                aoff ^= (aoff >> 3) & 0x70;
                uint32_t a0, a1, a2, a3;
                LDMX4(a0, a1, a2, a3, base + GS_AH + aoff);
                MMA16816(acc[mt][0], a0, a1, a2, a3, bh0, bh2);
                MMA16816(acc[mt][1], a0, a1, a2, a3, bh1, bh3);
            }
        }
    };

    issue_stage(0);
    issue_stage(1);
    for (int s = 0; s < NSTG; s++) {
        if (s + 1 < NSTG) CP_WAIT(1); else CP_WAIT(0);
        __syncthreads();
        compute_stage(s);
        if (s + 2 < NSTG) issue_stage(s + 2);
    }

    // ---------------- epilogue ----------------
    const int rrow = lid >> 2;
    const int cpair = (lid & 3) * 2;
    #pragma unroll
    for (int mt = 0; mt < 4; mt++) {
        #pragma unroll
        for (int nt = 0; nt < 2; nt++) {
            int n = n0 + wn * 16 + nt * 8 + cpair;
            if (MODE == 0) {
                #pragma unroll
                for (int hf = 0; hf < 2; hf++) {
                    int m = m0 + wm * 64 + mt * 16 + rrow + hf * 8;
                    *(float2*)(Dout + (size_t)m * EMB + n) =
                        make_float2(acc[mt][nt][2 * hf], acc[mt][nt][2 * hf + 1]);
                }
            } else {
                __half* Dh = (z == 0) ? Dh0 : (z == 1) ? Dh1 : Dh2;
                int h  = n >> 7;
                int dd = n & 127;
                float invf = powf(10000.0f, -(float)(dd >> 1) * (1.0f / 64.0f));
                #pragma unroll
                for (int hf = 0; hf < 2; hf++) {
                    int m = m0 + wm * 64 + mt * 16 + rrow + hf * 8;
                    int bb = m >> 11;
                    int sq = m & 2047;
                    float c0 = acc[mt][nt][2 * hf], c1 = acc[mt][nt][2 * hf + 1];
                    float v0 = c0, v1 = c1;
                    if (z < 2) {
                        float ang = (float)sq * invf;
                        float sn, cs;
                        sincosf(ang, &sn, &cs);
                        v0 = c0 * cs - c1 * sn;
                        v1 = c1 * cs + c0 * sn;
                    }
                    size_t idx = ((size_t)(bb * NHEAD + h) * SEQ + sq) * HDIM + dd;
                    uint32_t hp, lp;
                    split_hl(v0, v1, hp, lp);
                    *(uint32_t*)(Dh + idx) = hp;
                    if (z == 1) *(uint32_t*)(Dl1 + idx) = lp;   // K keeps residual of result
                }
            }
        }
    }
}

// =================================================================================
// Flash attention (unchanged from R9): S = Qh·(Kh+Kl); O = (Ph+Pl)·Vh
// smem: Qh 32K | 2 x (Kh 16K | Kl 16K | Vh 16K) = 128KB
// =================================================================================
#define FQH 0
#define FKV 32768
#define FKV_STRIDE 49152
#define FKH 0
#define FKL 16384
#define FVH 32768
#define FH_BYTES 131072

__device__ __forceinline__ uint32_t sw256(uint32_t off) {
    return off ^ ((off >> 4) & 0x70);
}

__global__ void __launch_bounds__(256, 1) flash_mma(
    const __half* __restrict__ Qh,
    const __half* __restrict__ Kh, const __half* __restrict__ Kl,
    const __half* __restrict__ Vh,
    __half* __restrict__ Ch)
{
    extern __shared__ char sm[];
    const uint32_t sb = smem_u32(sm);

    const int tid = threadIdx.x;
    const int wid = tid >> 5;
    const int lid = tid & 31;
    const int q0 = (gridDim.x - 1 - blockIdx.x) * 128;
    const int b  = blockIdx.y >> 4, h = blockIdx.y & 15;
    const size_t bh = ((size_t)(b * NHEAD + h)) * SEQ * HDIM;

    const int nIter = (q0 >> 6) + 2;

    auto issue_kv = [&](int it, int buf) {
        const int j0 = it * 64;
        const uint32_t base = sb + FKV + buf * FKV_STRIDE;
        #pragma unroll
        for (int i = 0; i < 4; i++) {
            int c = i * 256 + tid;
            int r = c >> 4, c16 = c & 15;
            uint32_t off = sw256((uint32_t)(r * 256 + c16 * 16));
            size_t src = bh + (size_t)(j0 + r) * HDIM + c16 * 8;
            CP_ASYNC16(base + FKH + off, Kh + src);
            CP_ASYNC16(base + FKL + off, Kl + src);
            CP_ASYNC16(base + FVH + off, Vh + src);
        }
        CP_COMMIT();
    };

    {
        #pragma unroll
        for (int i = 0; i < 8; i++) {
            int c = i * 256 + tid;
            int r = c >> 4, c16 = c & 15;
            uint32_t off = sw256((uint32_t)(r * 256 + c16 * 16));
            CP_ASYNC16(sb + FQH + off, Qh + bh + (size_t)(q0 + r) * HDIM + c16 * 8);
        }
    }
    issue_kv(0, 0);

    float os[16][4];
    #pragma unroll
    for (int i = 0; i < 16; i++)
        #pragma unroll
        for (int j = 0; j < 4; j++) os[i][j] = 0.f;
    float mrow[2] = {-1e30f, -1e30f};
    float lrow[2] = {0.f, 0.f};
    const float scale = 0.08838834764831845f;

    const int lr = lid & 15;
    const int lc = lid >> 4;

    for (int it = 0; it < nIter; it++) {
        const int j0 = it * 64;
        const int buf = it & 1;
        const uint32_t kbase = sb + FKV + buf * FKV_STRIDE;

        if (it + 1 < nIter) {
            issue_kv(it + 1, buf ^ 1);
            CP_WAIT(1);
        } else {
            CP_WAIT(0);
        }
        __syncthreads();

        if (j0 < q0 + (wid + 1) * 16) {
            float sacc[8][4];
            #pragma unroll
            for (int i = 0; i < 8; i++)
                #pragma unroll
                for (int j = 0; j < 4; j++) sacc[i][j] = 0.f;

            #pragma unroll
            for (int ks = 0; ks < 8; ks++) {
                uint32_t aoff = sw256((uint32_t)((wid * 16 + lr) * 256 + ks * 32 + lc * 16));
                uint32_t qh0, qh1, qh2, qh3;
                LDMX4(qh0, qh1, qh2, qh3, sb + FQH + aoff);
                #pragma unroll
                for (int bg = 0; bg < 4; bg++) {
                    uint32_t boff = sw256((uint32_t)((bg * 16 + lr) * 256 + ks * 32 + lc * 16));
                    uint32_t kh0, kh1, kh2, kh3, kl0, kl1, kl2, kl3;
                    LDMX4(kh0, kh1, kh2, kh3, kbase + FKH + boff);
                    LDMX4(kl0, kl1, kl2, kl3, kbase + FKL + boff);
                    MMA16816(sacc[bg * 2],     qh0, qh1, qh2, qh3, kh0, kh2);
                    MMA16816(sacc[bg * 2],     qh0, qh1, qh2, qh3, kl0, kl2);
                    MMA16816(sacc[bg * 2 + 1], qh0, qh1, qh2, qh3, kh1, kh3);
                    MMA16816(sacc[bg * 2 + 1], qh0, qh1, qh2, qh3, kl1, kl3);
                }
            }

            const int r0g = q0 + wid * 16 + (lid >> 2);
            const int c0g = j0 + 2 * (lid & 3);
            #pragma unroll
            for (int nt = 0; nt < 8; nt++)
                #pragma unroll
                for (int c = 0; c < 4; c++) {
                    int rr = r0g + ((c >= 2) ? 8 : 0);
                    int cc = c0g + nt * 8 + (c & 1);
                    float v = sacc[nt][c] * scale;
                    if (cc > rr) v = -1e30f;
                    sacc[nt][c] = v;
                }

            float mx0 = -1e30f, mx1 = -1e30f;
            #pragma unroll
            for (int nt = 0; nt < 8; nt++) {
                mx0 = fmaxf(mx0, fmaxf(sacc[nt][0], sacc[nt][1]));
                mx1 = fmaxf(mx1, fmaxf(sacc[nt][2], sacc[nt][3]));
            }
            #pragma unroll
            for (int o = 1; o < 4; o <<= 1) {
                mx0 = fmaxf(mx0, __shfl_xor_sync(0xffffffffu, mx0, o));
                mx1 = fmaxf(mx1, __shfl_xor_sync(0xffffffffu, mx1, o));
            }
            float mn0 = fmaxf(mrow[0], mx0);
            float mn1 = fmaxf(mrow[1], mx1);
            float cr0 = __expf(mrow[0] - mn0);
            float cr1 = __expf(mrow[1] - mn1);
            float rs0 = 0.f, rs1 = 0.f;
            #pragma unroll
            for (int nt = 0; nt < 8; nt++) {
                float p0 = __expf(sacc[nt][0] - mn0);
                float p1 = __expf(sacc[nt][1] - mn0);
                float p2 = __expf(sacc[nt][2] - mn1);
                float p3 = __expf(sacc[nt][3] - mn1);
                sacc[nt][0] = p0; sacc[nt][1] = p1; sacc[nt][2] = p2; sacc[nt][3] = p3;
                rs0 += p0 + p1; rs1 += p2 + p3;
            }
            #pragma unroll
            for (int o = 1; o < 4; o <<= 1) {
                rs0 += __shfl_xor_sync(0xffffffffu, rs0, o);
                rs1 += __shfl_xor_sync(0xffffffffu, rs1, o);
            }
            lrow[0] = lrow[0] * cr0 + rs0;
            lrow[1] = lrow[1] * cr1 + rs1;
            mrow[0] = mn0; mrow[1] = mn1;
            #pragma unroll
            for (int nt = 0; nt < 16; nt++) {
                os[nt][0] *= cr0; os[nt][1] *= cr0;
                os[nt][2] *= cr1; os[nt][3] *= cr1;
            }

            #pragma unroll
            for (int kt = 0; kt < 4; kt++) {
                uint32_t ah[4], al[4];
                #pragma unroll
                for (int q = 0; q < 4; q++) {
                    int nt = 2 * kt + (q >> 1);
                    int cc = (q & 1) * 2;
                    split_hl(sacc[nt][cc], sacc[nt][cc + 1], ah[q], al[q]);
                }
                const int vrow = kt * 16 + (lid & 7) + ((lid >> 3) & 1) * 8;
                const int vnh  = (lid >> 4) * 8;
                #pragma unroll
                for (int bg2 = 0; bg2 < 8; bg2++) {
                    uint32_t voff = sw256((uint32_t)(vrow * 256 + (bg2 * 16 + vnh) * 2));
                    uint32_t vh0, vh1, vh2, vh3;
                    LDMX4T(vh0, vh1, vh2, vh3, kbase + FVH + voff);
                    MMA16816(os[bg2 * 2],     ah[0], ah[1], ah[2], ah[3], vh0, vh1);
                    MMA16816(os[bg2 * 2],     al[0], al[1], al[2], al[3], vh0, vh1);
                    MMA16816(os[bg2 * 2 + 1], ah[0], ah[1], ah[2], ah[3], vh2, vh3);
                    MMA16816(os[bg2 * 2 + 1], al[0], al[1], al[2], al[3], vh2, vh3);
                }
            }
        }
        __syncthreads();
    }

    const float inv0 = 1.0f / lrow[0];
    const float inv1 = 1.0f / lrow[1];
    const int row0 = q0 + wid * 16 + (lid >> 2);
    const int dbase = 2 * (lid & 3);
    #pragma unroll
    for (int nt = 0; nt < 16; nt++) {
        int d = nt * 8 + dbase;
        size_t i0 = ((size_t)(b * SEQ + row0))     * EMB + h * HDIM + d;
        size_t i1 = ((size_t)(b * SEQ + row0 + 8)) * EMB + h * HDIM + d;
        *(uint32_t*)(Ch + i0) = pack_h2(__float2half_rn(os[nt][0] * inv0),
                                        __float2half_rn(os[nt][1] * inv0));
        *(uint32_t*)(Ch + i1) = pack_h2(__float2half_rn(os[nt][2] * inv1),
                                        __float2half_rn(os[nt][3] * inv1));
    }
}

// =================================================================================
extern "C" void kernel_launch(void* const* d_in, const int* in_sizes, int n_in,
                              void* d_out, int out_size)
{
    const float* x  = (const float*)d_in[0];
    const float* Wq = (const float*)d_in[1];
    const float* Wk = (const float*)d_in[2];
    const float* Wv = (const float*)d_in[3];
    const float* Wo = (const float*)d_in[4];
    float* out = (float*)d_out;

    __half *xh, *Wh, *Qh, *Kh, *Kl, *Vh, *Ch;
    cudaGetSymbolAddress((void**)&xh, g_xh);
    cudaGetSymbolAddress((void**)&Wh, g_Wh);
    cudaGetSymbolAddress((void**)&Qh, g_Qh);
    cudaGetSymbolAddress((void**)&Kh, g_Kh);
    cudaGetSymbolAddress((void**)&Kl, g_Kl);
    cudaGetSymbolAddress((void**)&Vh, g_Vh);
    cudaGetSymbolAddress((void**)&Ch, g_Ch);

    cudaFuncSetAttribute(gemm_hl<1>, cudaFuncAttributeMaxDynamicSharedMemorySize, GSM);
    cudaFuncSetAttribute(gemm_hl<0>, cudaFuncAttributeMaxDynamicSharedMemorySize, GSM);
    cudaFuncSetAttribute(flash_mma, cudaFuncAttributeMaxDynamicSharedMemorySize, FH_BYTES);

    // 0) fused pre-convert (hi only)
    conv_all<<<XB + 4 * WB, 256>>>(x, Wq, Wk, Wv, Wo, xh, Wh);

    // 1) QKV projection (single-pass fp16) + RoPE; Q,V hi; K hi+lo of result
    {
        dim3 grid(EMB / BN, MTOT / BM, 3);
        gemm_hl<1><<<grid, 256, GSM>>>(
            xh,
            Wh + 0 * (size_t)NELEM_W,
            Wh + 1 * (size_t)NELEM_W,
            Wh + 2 * (size_t)NELEM_W,
            Qh, Kh, Kl, Vh, nullptr);
    }
    // 2) causal flash attention (asymmetric 2-pass) -> context hi
    {
        dim3 grid(SEQ / 128, BATCH * NHEAD);
        flash_mma<<<grid, 256, FH_BYTES>>>(Qh, Kh, Kl, Vh, Ch);
    }
    // 3) output projection (single-pass fp16) -> fp32 out
    {
        dim3 grid(EMB / BN, MTOT / BM, 1);
        gemm_hl<0><<<grid, 256, GSM>>>(
            Ch,
            Wh + 3 * (size_t)NELEM_W, nullptr, nullptr,
            nullptr, nullptr, nullptr, nullptr, out);
    }
}

// round 11
// speedup vs baseline: 2.3290x; 1.0605x over previous
#include <cuda_runtime.h>
#include <cuda_fp16.h>
#include <math.h>
#include <stdint.h>

#define BATCH  4
#define SEQ    2048
#define EMB    2048
#define NHEAD  16
#define HDIM   128
#define MTOT   (BATCH*SEQ)      // 8192
#define KDIM   2048
#define NELEM_X (MTOT*KDIM)     // 16.8M
#define NELEM_W (KDIM*KDIM)     // 4.19M

// ---------------- scratch (device globals: allocation-free rule) ----------------
__device__ __half g_xh[NELEM_X];
__device__ __half g_Wh[4][NELEM_W];
__device__ __half g_Qh[NELEM_X];
__device__ __half g_Kh[NELEM_X], g_Kl[NELEM_X];
__device__ __half g_Vh[NELEM_X];
__device__ __half g_Ch[NELEM_X];

__device__ __forceinline__ uint32_t smem_u32(const void* p) {
    uint32_t a;
    asm("{ .reg .u64 t; cvta.to.shared.u64 t, %1; cvt.u32.u64 %0, t; }" : "=r"(a) : "l"(p));
    return a;
}

#define CP_ASYNC16(dst, src) \
    asm volatile("cp.async.cg.shared.global [%0], [%1], 16;" :: "r"(dst), "l"(src))
#define CP_COMMIT() asm volatile("cp.async.commit_group;" ::: "memory")
#define CP_WAIT(n)  asm volatile("cp.async.wait_group %0;" :: "n"(n) : "memory")

#define LDMX4(r0,r1,r2,r3, addr) \
    asm volatile("ldmatrix.sync.aligned.m8n8.x4.shared.b16 {%0,%1,%2,%3}, [%4];" \
        : "=r"(r0),"=r"(r1),"=r"(r2),"=r"(r3) : "r"(addr))
#define LDMX4T(r0,r1,r2,r3, addr) \
    asm volatile("ldmatrix.sync.aligned.m8n8.x4.trans.shared.b16 {%0,%1,%2,%3}, [%4];" \
        : "=r"(r0),"=r"(r1),"=r"(r2),"=r"(r3) : "r"(addr))

#define MMA16816(c, a0,a1,a2,a3, b0,b1) \
    asm volatile("mma.sync.aligned.m16n8k16.row.col.f32.f16.f16.f32 " \
        "{%0,%1,%2,%3}, {%4,%5,%6,%7}, {%8,%9}, {%0,%1,%2,%3};" \
        : "+f"((c)[0]),"+f"((c)[1]),"+f"((c)[2]),"+f"((c)[3]) \
        : "r"(a0),"r"(a1),"r"(a2),"r"(a3), "r"(b0),"r"(b1))

__device__ __forceinline__ uint32_t pack_h2(__half x, __half y) {
    __half2 h = __halves2half2(x, y);
    return *(uint32_t*)&h;
}
__device__ __forceinline__ void split_hl(float x, float y, uint32_t& hp, uint32_t& lp) {
    __half hx = __float2half_rn(x), hy = __float2half_rn(y);
    hp = pack_h2(hx, hy);
    lp = pack_h2(__float2half_rn(x - __half2float(hx)),
                 __float2half_rn(y - __half2float(hy)));
}

// =================================================================================
// fused pre-convert: x and all W -> fp16 hi only.
// =================================================================================
#define XB (NELEM_X/2048)
#define WB (NELEM_W/2048)

__global__ void __launch_bounds__(256) conv_all(
    const float* __restrict__ x,
    const float* __restrict__ Wq, const float* __restrict__ Wk,
    const float* __restrict__ Wv, const float* __restrict__ Wo,
    __half* __restrict__ xh, __half* __restrict__ Wh)
{
    int blk = blockIdx.x;
    const float* s;
    __half* h;
    if (blk < XB) {
        s = x; h = xh;
    } else {
        int wi = (blk - XB) / WB;
        blk = (blk - XB) % WB;
        s = (wi == 0) ? Wq : (wi == 1) ? Wk : (wi == 2) ? Wv : Wo;
        h = Wh + (size_t)wi * NELEM_W;
    }
    int i0 = blk * 512 + threadIdx.x;
    #pragma unroll
    for (int k = 0; k < 2; k++) {
        int i = i0 + k * 256;
        float4 v = ((const float4*)s)[i];
        uint2 hp;
        hp.x = pack_h2(__float2half_rn(v.x), __float2half_rn(v.y));
        hp.y = pack_h2(__float2half_rn(v.z), __float2half_rn(v.w));
        ((uint2*)h)[i] = hp;
    }
}

// =================================================================================
// single-pass fp16 mma GEMM: C[m,n] = sum_k Ah[m,k]*Wh[n,k]
// BM=128, BN=128, BK=64; 8 warps 2(M)x4(N) -> 64x32 warp tile;
// 3-stage cp.async ring; one sync/stage; 32KB/stage -> 96KB -> 2 CTAs/SM.
// MODE 0: fp32 store.  MODE 1: QKV (z), RoPE for z<2; Q,V hi; K hi+lo (of result).
// =================================================================================
#define BM 128
#define BN 128
#define BK 64
#define NSTG (KDIM/BK)     // 32

#define GS_AH 0
#define GS_BH 16384
#define GS_STRIDE 32768
#define GSM (3*GS_STRIDE)   // 96KB

template<int MODE>
__global__ void __launch_bounds__(256, 2) gemm_hl(
    const __half* __restrict__ Ah,
    const __half* __restrict__ Bh0, const __half* __restrict__ Bh1,
    const __half* __restrict__ Bh2,
    __half* __restrict__ Dh0,
    __half* __restrict__ Dh1, __half* __restrict__ Dl1,
    __half* __restrict__ Dh2,
    float* __restrict__ Dout)
{
    extern __shared__ char sm[];
    const uint32_t sb = smem_u32(sm);

    const __half* Bh = Bh0;
    int z = 0;
    if (MODE == 1) {
        z = blockIdx.z;
        if (z == 1) Bh = Bh1;
        else if (z == 2) Bh = Bh2;
    }

    const int tid = threadIdx.x;
    const int wid = tid >> 5;
    const int lid = tid & 31;
    const int wm = wid >> 2;        // 0..1 -> 64 M-rows each
    const int wn = wid & 3;         // 0..3 -> 32 N-cols each
    const int m0 = blockIdx.y * BM;
    const int n0 = blockIdx.x * BN;

    float acc[4][4][4];             // [m16][n8][frag]
    #pragma unroll
    for (int i = 0; i < 4; i++)
        #pragma unroll
        for (int j = 0; j < 4; j++)
            #pragma unroll
            for (int k = 0; k < 4; k++) acc[i][j][k] = 0.f;

    // 8 cp.async chunks/thread/stage: A 1024 chunks + B 1024 chunks
    auto issue_stage = [&](int s) {
        const int kt = s * BK;
        const uint32_t base = sb + (uint32_t)(s % 3) * GS_STRIDE;
        #pragma unroll
        for (int i = 0; i < 4; i++) {
            int c = i * 256 + tid;
            int r = c >> 3, c16 = c & 7;
            uint32_t off = (uint32_t)(r * 128 + c16 * 16);
            off ^= (off >> 3) & 0x70;
            CP_ASYNC16(base + GS_AH + off, Ah + (size_t)(m0 + r) * KDIM + kt + c16 * 8);
            CP_ASYNC16(base + GS_BH + off, Bh + (size_t)(n0 + r) * KDIM + kt + c16 * 8);
        }
        CP_COMMIT();
    };

    auto compute_stage = [&](int s) {
        const uint32_t base = sb + (uint32_t)(s % 3) * GS_STRIDE;
        const int lr = lid & 15;
        const int lc = lid >> 4;
        #pragma unroll
        for (int ks = 0; ks < 4; ks++) {
            uint32_t bf[2][4];
            #pragma unroll
            for (int bt = 0; bt < 2; bt++) {
                uint32_t boff = (uint32_t)((wn * 32 + bt * 16 + lr) * 128 + ks * 32 + lc * 16);
                boff ^= (boff >> 3) & 0x70;
                LDMX4(bf[bt][0], bf[bt][1], bf[bt][2], bf[bt][3], base + GS_BH + boff);
            }
            #pragma unroll
            for (int mt = 0; mt < 4; mt++) {
                uint32_t aoff = (uint32_t)((wm * 64 + mt * 16 + lr) * 128 + ks * 32 + lc * 16);
                aoff ^= (aoff >> 3) & 0x70;
                uint32_t a0, a1, a2, a3;
                LDMX4(a0, a1, a2, a3, base + GS_AH + aoff);
                #pragma unroll
                for (int bt = 0; bt < 2; bt++) {
                    MMA16816(acc[mt][bt * 2],     a0, a1, a2, a3, bf[bt][0], bf[bt][2]);
                    MMA16816(acc[mt][bt * 2 + 1], a0, a1, a2, a3, bf[bt][1], bf[bt][3]);
                }
            }
        }
    };

    issue_stage(0);
    issue_stage(1);
    for (int s = 0; s < NSTG; s++) {
        if (s + 1 < NSTG) CP_WAIT(1); else CP_WAIT(0);
        __syncthreads();
        compute_stage(s);
        if (s + 2 < NSTG) issue_stage(s + 2);
    }

    // ---------------- epilogue ----------------
    const int rrow = lid >> 2;
    const int cpair = (lid & 3) * 2;
    #pragma unroll
    for (int mt = 0; mt < 4; mt++) {
        #pragma unroll
        for (int j = 0; j < 4; j++) {
            int n = n0 + wn * 32 + j * 8 + cpair;
            if (MODE == 0) {
                #pragma unroll
                for (int hf = 0; hf < 2; hf++) {
                    int m = m0 + wm * 64 + mt * 16 + rrow + hf * 8;
                    *(float2*)(Dout + (size_t)m * EMB + n) =
                        make_float2(acc[mt][j][2 * hf], acc[mt][j][2 * hf + 1]);
                }
            } else {
                __half* Dh = (z == 0) ? Dh0 : (z == 1) ? Dh1 : Dh2;
                int h  = n >> 7;
                int dd = n & 127;
                float invf = powf(10000.0f, -(float)(dd >> 1) * (1.0f / 64.0f));
                #pragma unroll
                for (int hf = 0; hf < 2; hf++) {
                    int m = m0 + wm * 64 + mt * 16 + rrow + hf * 8;
                    int bb = m >> 11;
                    int sq = m & 2047;
                    float c0 = acc[mt][j][2 * hf], c1 = acc[mt][j][2 * hf + 1];
                    float v0 = c0, v1 = c1;
                    if (z < 2) {
                        float ang = (float)sq * invf;
                        float sn, cs;
                        sincosf(ang, &sn, &cs);
                        v0 = c0 * cs - c1 * sn;
                        v1 = c1 * cs + c0 * sn;
                    }
                    size_t idx = ((size_t)(bb * NHEAD + h) * SEQ + sq) * HDIM + dd;
                    uint32_t hp, lp;
                    split_hl(v0, v1, hp, lp);
                    *(uint32_t*)(Dh + idx) = hp;
                    if (z == 1) *(uint32_t*)(Dl1 + idx) = lp;   // K keeps residual of result
                }
            }
        }
    }
}

// =================================================================================
// Flash attention (unchanged from R10): S = Qh·(Kh+Kl); O = (Ph+Pl)·Vh
// smem: Qh 32K | 2 x (Kh 16K | Kl 16K | Vh 16K) = 128KB
// =================================================================================
#define FQH 0
#define FKV 32768
#define FKV_STRIDE 49152
#define FKH 0
#define FKL 16384
#define FVH 32768
#define FH_BYTES 131072

__device__ __forceinline__ uint32_t sw256(uint32_t off) {
    return off ^ ((off >> 4) & 0x70);
}

__global__ void __launch_bounds__(256, 1) flash_mma(
    const __half* __restrict__ Qh,
    const __half* __restrict__ Kh, const __half* __restrict__ Kl,
    const __half* __restrict__ Vh,
    __half* __restrict__ Ch)
{
    extern __shared__ char sm[];
    const uint32_t sb = smem_u32(sm);

    const int tid = threadIdx.x;
    const int wid = tid >> 5;
    const int lid = tid & 31;
    const int q0 = (gridDim.x - 1 - blockIdx.x) * 128;
    const int b  = blockIdx.y >> 4, h = blockIdx.y & 15;
    const size_t bh = ((size_t)(b * NHEAD + h)) * SEQ * HDIM;

    const int nIter = (q0 >> 6) + 2;

    auto issue_kv = [&](int it, int buf) {
        const int j0 = it * 64;
        const uint32_t base = sb + FKV + buf * FKV_STRIDE;
        #pragma unroll
        for (int i = 0; i < 4; i++) {
            int c = i * 256 + tid;
            int r = c >> 4, c16 = c & 15;
            uint32_t off = sw256((uint32_t)(r * 256 + c16 * 16));
            size_t src = bh + (size_t)(j0 + r) * HDIM + c16 * 8;
            CP_ASYNC16(base + FKH + off, Kh + src);
            CP_ASYNC16(base + FKL + off, Kl + src);
            CP_ASYNC16(base + FVH + off, Vh + src);
        }
        CP_COMMIT();
    };

    {
        #pragma unroll
        for (int i = 0; i < 8; i++) {
            int c = i * 256 + tid;
            int r = c >> 4, c16 = c & 15;
            uint32_t off = sw256((uint32_t)(r * 256 + c16 * 16));
            CP_ASYNC16(sb + FQH + off, Qh + bh + (size_t)(q0 + r) * HDIM + c16 * 8);
        }
    }
    issue_kv(0, 0);

    float os[16][4];
    #pragma unroll
    for (int i = 0; i < 16; i++)
        #pragma unroll
        for (int j = 0; j < 4; j++) os[i][j] = 0.f;
    float mrow[2] = {-1e30f, -1e30f};
    float lrow[2] = {0.f, 0.f};
    const float scale = 0.08838834764831845f;

    const int lr = lid & 15;
    const int lc = lid >> 4;

    for (int it = 0; it < nIter; it++) {
        const int j0 = it * 64;
        const int buf = it & 1;
        const uint32_t kbase = sb + FKV + buf * FKV_STRIDE;

        if (it + 1 < nIter) {
            issue_kv(it + 1, buf ^ 1);
            CP_WAIT(1);
        } else {
            CP_WAIT(0);
        }
        __syncthreads();

        if (j0 < q0 + (wid + 1) * 16) {
            float sacc[8][4];
            #pragma unroll
            for (int i = 0; i < 8; i++)
                #pragma unroll
                for (int j = 0; j < 4; j++) sacc[i][j] = 0.f;

            #pragma unroll
            for (int ks = 0; ks < 8; ks++) {
                uint32_t aoff = sw256((uint32_t)((wid * 16 + lr) * 256 + ks * 32 + lc * 16));
                uint32_t qh0, qh1, qh2, qh3;
                LDMX4(qh0, qh1, qh2, qh3, sb + FQH + aoff);
                #pragma unroll
                for (int bg = 0; bg < 4; bg++) {
                    uint32_t boff = sw256((uint32_t)((bg * 16 + lr) * 256 + ks * 32 + lc * 16));
                    uint32_t kh0, kh1, kh2, kh3, kl0, kl1, kl2, kl3;
                    LDMX4(kh0, kh1, kh2, kh3, kbase + FKH + boff);
                    LDMX4(kl0, kl1, kl2, kl3, kbase + FKL + boff);
                    MMA16816(sacc[bg * 2],     qh0, qh1, qh2, qh3, kh0, kh2);
                    MMA16816(sacc[bg * 2],     qh0, qh1, qh2, qh3, kl0, kl2);
                    MMA16816(sacc[bg * 2 + 1], qh0, qh1, qh2, qh3, kh1, kh3);
                    MMA16816(sacc[bg * 2 + 1], qh0, qh1, qh2, qh3, kl1, kl3);
                }
            }

            const int r0g = q0 + wid * 16 + (lid >> 2);
            const int c0g = j0 + 2 * (lid & 3);
            #pragma unroll
            for (int nt = 0; nt < 8; nt++)
                #pragma unroll
                for (int c = 0; c < 4; c++) {
                    int rr = r0g + ((c >= 2) ? 8 : 0);
                    int cc = c0g + nt * 8 + (c & 1);
                    float v = sacc[nt][c] * scale;
                    if (cc > rr) v = -1e30f;
                    sacc[nt][c] = v;
                }

            float mx0 = -1e30f, mx1 = -1e30f;
            #pragma unroll
            for (int nt = 0; nt < 8; nt++) {
                mx0 = fmaxf(mx0, fmaxf(sacc[nt][0], sacc[nt][1]));
                mx1 = fmaxf(mx1, fmaxf(sacc[nt][2], sacc[nt][3]));
            }
            #pragma unroll
            for (int o = 1; o < 4; o <<= 1) {
                mx0 = fmaxf(mx0, __shfl_xor_sync(0xffffffffu, mx0, o));
                mx1 = fmaxf(mx1, __shfl_xor_sync(0xffffffffu, mx1, o));
            }
            float mn0 = fmaxf(mrow[0], mx0);
            float mn1 = fmaxf(mrow[1], mx1);
            float cr0 = __expf(mrow[0] - mn0);
            float cr1 = __expf(mrow[1] - mn1);
            float rs0 = 0.f, rs1 = 0.f;
            #pragma unroll
            for (int nt = 0; nt < 8; nt++) {
                float p0 = __expf(sacc[nt][0] - mn0);
                float p1 = __expf(sacc[nt][1] - mn0);
                float p2 = __expf(sacc[nt][2] - mn1);
                float p3 = __expf(sacc[nt][3] - mn1);
                sacc[nt][0] = p0; sacc[nt][1] = p1; sacc[nt][2] = p2; sacc[nt][3] = p3;
                rs0 += p0 + p1; rs1 += p2 + p3;
            }
            #pragma unroll
            for (int o = 1; o < 4; o <<= 1) {
                rs0 += __shfl_xor_sync(0xffffffffu, rs0, o);
                rs1 += __shfl_xor_sync(0xffffffffu, rs1, o);
            }
            lrow[0] = lrow[0] * cr0 + rs0;
            lrow[1] = lrow[1] * cr1 + rs1;
            mrow[0] = mn0; mrow[1] = mn1;
            #pragma unroll
            for (int nt = 0; nt < 16; nt++) {
                os[nt][0] *= cr0; os[nt][1] *= cr0;
                os[nt][2] *= cr1; os[nt][3] *= cr1;
            }

            #pragma unroll
            for (int kt = 0; kt < 4; kt++) {
                uint32_t ah[4], al[4];
                #pragma unroll
                for (int q = 0; q < 4; q++) {
                    int nt = 2 * kt + (q >> 1);
                    int cc = (q & 1) * 2;
                    split_hl(sacc[nt][cc], sacc[nt][cc + 1], ah[q], al[q]);
                }
                const int vrow = kt * 16 + (lid & 7) + ((lid >> 3) & 1) * 8;
                const int vnh  = (lid >> 4) * 8;
                #pragma unroll
                for (int bg2 = 0; bg2 < 8; bg2++) {
                    uint32_t voff = sw256((uint32_t)(vrow * 256 + (bg2 * 16 + vnh) * 2));
                    uint32_t vh0, vh1, vh2, vh3;
                    LDMX4T(vh0, vh1, vh2, vh3, kbase + FVH + voff);
                    MMA16816(os[bg2 * 2],     ah[0], ah[1], ah[2], ah[3], vh0, vh1);
                    MMA16816(os[bg2 * 2],     al[0], al[1], al[2], al[3], vh0, vh1);
                    MMA16816(os[bg2 * 2 + 1], ah[0], ah[1], ah[2], ah[3], vh2, vh3);
                    MMA16816(os[bg2 * 2 + 1], al[0], al[1], al[2], al[3], vh2, vh3);
                }
            }
        }
        __syncthreads();
    }

    const float inv0 = 1.0f / lrow[0];
    const float inv1 = 1.0f / lrow[1];
    const int row0 = q0 + wid * 16 + (lid >> 2);
    const int dbase = 2 * (lid & 3);
    #pragma unroll
    for (int nt = 0; nt < 16; nt++) {
        int d = nt * 8 + dbase;
        size_t i0 = ((size_t)(b * SEQ + row0))     * EMB + h * HDIM + d;
        size_t i1 = ((size_t)(b * SEQ + row0 + 8)) * EMB + h * HDIM + d;
        *(uint32_t*)(Ch + i0) = pack_h2(__float2half_rn(os[nt][0] * inv0),
                                        __float2half_rn(os[nt][1] * inv0));
        *(uint32_t*)(Ch + i1) = pack_h2(__float2half_rn(os[nt][2] * inv1),
                                        __float2half_rn(os[nt][3] * inv1));
    }
}

// =================================================================================
extern "C" void kernel_launch(void* const* d_in, const int* in_sizes, int n_in,
                              void* d_out, int out_size)
{
    const float* x  = (const float*)d_in[0];
    const float* Wq = (const float*)d_in[1];
    const float* Wk = (const float*)d_in[2];
    const float* Wv = (const float*)d_in[3];
    const float* Wo = (const float*)d_in[4];
    float* out = (float*)d_out;

    __half *xh, *Wh, *Qh, *Kh, *Kl, *Vh, *Ch;
    cudaGetSymbolAddress((void**)&xh, g_xh);
    cudaGetSymbolAddress((void**)&Wh, g_Wh);
    cudaGetSymbolAddress((void**)&Qh, g_Qh);
    cudaGetSymbolAddress((void**)&Kh, g_Kh);
    cudaGetSymbolAddress((void**)&Kl, g_Kl);
    cudaGetSymbolAddress((void**)&Vh, g_Vh);
    cudaGetSymbolAddress((void**)&Ch, g_Ch);

    cudaFuncSetAttribute(gemm_hl<1>, cudaFuncAttributeMaxDynamicSharedMemorySize, GSM);
    cudaFuncSetAttribute(gemm_hl<0>, cudaFuncAttributeMaxDynamicSharedMemorySize, GSM);
    cudaFuncSetAttribute(flash_mma, cudaFuncAttributeMaxDynamicSharedMemorySize, FH_BYTES);

    // 0) fused pre-convert (hi only)
    conv_all<<<XB + 4 * WB, 256>>>(x, Wq, Wk, Wv, Wo, xh, Wh);

    // 1) QKV projection (single-pass fp16, BN=128) + RoPE; Q,V hi; K hi+lo of result
    {
        dim3 grid(EMB / BN, MTOT / BM, 3);
        gemm_hl<1><<<grid, 256, GSM>>>(
            xh,
            Wh + 0 * (size_t)NELEM_W,
            Wh + 1 * (size_t)NELEM_W,
            Wh + 2 * (size_t)NELEM_W,
            Qh, Kh, Kl, Vh, nullptr);
    }
    // 2) causal flash attention (asymmetric 2-pass) -> context hi
    {
        dim3 grid(SEQ / 128, BATCH * NHEAD);
        flash_mma<<<grid, 256, FH_BYTES>>>(Qh, Kh, Kl, Vh, Ch);
    }
    // 3) output projection (single-pass fp16, BN=128) -> fp32 out
    {
        dim3 grid(EMB / BN, MTOT / BM, 1);
        gemm_hl<0><<<grid, 256, GSM>>>(
            Ch,
            Wh + 3 * (size_t)NELEM_W, nullptr, nullptr,
            nullptr, nullptr, nullptr, nullptr, out);
    }
}

// round 12
// speedup vs baseline: 2.5405x; 1.0908x over previous
#include <cuda_runtime.h>
#include <cuda_fp16.h>
#include <math.h>
#include <stdint.h>

#define BATCH  4
#define SEQ    2048
#define EMB    2048
#define NHEAD  16
#define HDIM   128
#define MTOT   (BATCH*SEQ)      // 8192
#define KDIM   2048
#define NELEM_X (MTOT*KDIM)     // 16.8M
#define NELEM_W (KDIM*KDIM)     // 4.19M

// ---------------- scratch (device globals: allocation-free rule) ----------------
__device__ __half g_xh[NELEM_X];
__device__ __half g_Wh[4][NELEM_W];
__device__ __half g_Qh[NELEM_X];
__device__ __half g_Kh[NELEM_X];
__device__ __half g_Vh[NELEM_X];
__device__ __half g_Ch[NELEM_X];

__device__ __forceinline__ uint32_t smem_u32(const void* p) {
    uint32_t a;
    asm("{ .reg .u64 t; cvta.to.shared.u64 t, %1; cvt.u32.u64 %0, t; }" : "=r"(a) : "l"(p));
    return a;
}

#define CP_ASYNC16(dst, src) \
    asm volatile("cp.async.cg.shared.global [%0], [%1], 16;" :: "r"(dst), "l"(src))
#define CP_COMMIT() asm volatile("cp.async.commit_group;" ::: "memory")
#define CP_WAIT(n)  asm volatile("cp.async.wait_group %0;" :: "n"(n) : "memory")

#define LDMX4(r0,r1,r2,r3, addr) \
    asm volatile("ldmatrix.sync.aligned.m8n8.x4.shared.b16 {%0,%1,%2,%3}, [%4];" \
        : "=r"(r0),"=r"(r1),"=r"(r2),"=r"(r3) : "r"(addr))
#define LDMX4T(r0,r1,r2,r3, addr) \
    asm volatile("ldmatrix.sync.aligned.m8n8.x4.trans.shared.b16 {%0,%1,%2,%3}, [%4];" \
        : "=r"(r0),"=r"(r1),"=r"(r2),"=r"(r3) : "r"(addr))

#define MMA16816(c, a0,a1,a2,a3, b0,b1) \
    asm volatile("mma.sync.aligned.m16n8k16.row.col.f32.f16.f16.f32 " \
        "{%0,%1,%2,%3}, {%4,%5,%6,%7}, {%8,%9}, {%0,%1,%2,%3};" \
        : "+f"((c)[0]),"+f"((c)[1]),"+f"((c)[2]),"+f"((c)[3]) \
        : "r"(a0),"r"(a1),"r"(a2),"r"(a3), "r"(b0),"r"(b1))

__device__ __forceinline__ uint32_t pack_h2(__half x, __half y) {
    __half2 h = __halves2half2(x, y);
    return *(uint32_t*)&h;
}
__device__ __forceinline__ void split_hl(float x, float y, uint32_t& hp, uint32_t& lp) {
    __half hx = __float2half_rn(x), hy = __float2half_rn(y);
    hp = pack_h2(hx, hy);
    lp = pack_h2(__float2half_rn(x - __half2float(hx)),
                 __float2half_rn(y - __half2float(hy)));
}

// =================================================================================
// fused pre-convert: x and all W -> fp16 (4 x float4 per thread for MLP)
// =================================================================================
#define XB (NELEM_X/4096)   // 4096 blocks
#define WB (NELEM_W/4096)   // 1024 blocks per W

__global__ void __launch_bounds__(256) conv_all(
    const float* __restrict__ x,
    const float* __restrict__ Wq, const float* __restrict__ Wk,
    const float* __restrict__ Wv, const float* __restrict__ Wo,
    __half* __restrict__ xh, __half* __restrict__ Wh)
{
    int blk = blockIdx.x;
    const float* s;
    __half* h;
    if (blk < XB) {
        s = x; h = xh;
    } else {
        int wi = (blk - XB) / WB;
        blk = (blk - XB) % WB;
        s = (wi == 0) ? Wq : (wi == 1) ? Wk : (wi == 2) ? Wv : Wo;
        h = Wh + (size_t)wi * NELEM_W;
    }
    int i0 = blk * 1024 + threadIdx.x;
    #pragma unroll
    for (int k = 0; k < 4; k++) {
        int i = i0 + k * 256;
        float4 v = ((const float4*)s)[i];
        uint2 hp;
        hp.x = pack_h2(__float2half_rn(v.x), __float2half_rn(v.y));
        hp.y = pack_h2(__float2half_rn(v.z), __float2half_rn(v.w));
        ((uint2*)h)[i] = hp;
    }
}

// =================================================================================
// single-pass fp16 mma GEMM: C[m,n] = sum_k Ah[m,k]*Wh[n,k]
// BM=128, BN=128, BK=64; 8 warps 2(M)x4(N); 3-stage ring; 2 CTAs/SM. (R11)
// MODE 0: fp32 store.  MODE 1: QKV (z), RoPE for z<2, fp16 hi store [B,H,S,D].
// =================================================================================
#define BM 128
#define BN 128
#define BK 64
#define NSTG (KDIM/BK)     // 32

#define GS_AH 0
#define GS_BH 16384
#define GS_STRIDE 32768
#define GSM (3*GS_STRIDE)   // 96KB

template<int MODE>
__global__ void __launch_bounds__(256, 2) gemm_hl(
    const __half* __restrict__ Ah,
    const __half* __restrict__ Bh0, const __half* __restrict__ Bh1,
    const __half* __restrict__ Bh2,
    __half* __restrict__ Dh0, __half* __restrict__ Dh1, __half* __restrict__ Dh2,
    float* __restrict__ Dout)
{
    extern __shared__ char sm[];
    const uint32_t sb = smem_u32(sm);

    const __half* Bh = Bh0;
    int z = 0;
    if (MODE == 1) {
        z = blockIdx.z;
        if (z == 1) Bh = Bh1;
        else if (z == 2) Bh = Bh2;
    }

    const int tid = threadIdx.x;
    const int wid = tid >> 5;
    const int lid = tid & 31;
    const int wm = wid >> 2;
    const int wn = wid & 3;
    const int m0 = blockIdx.y * BM;
    const int n0 = blockIdx.x * BN;

    float acc[4][4][4];
    #pragma unroll
    for (int i = 0; i < 4; i++)
        #pragma unroll
        for (int j = 0; j < 4; j++)
            #pragma unroll
            for (int k = 0; k < 4; k++) acc[i][j][k] = 0.f;

    auto issue_stage = [&](int s) {
        const int kt = s * BK;
        const uint32_t base = sb + (uint32_t)(s % 3) * GS_STRIDE;
        #pragma unroll
        for (int i = 0; i < 4; i++) {
            int c = i * 256 + tid;
            int r = c >> 3, c16 = c & 7;
            uint32_t off = (uint32_t)(r * 128 + c16 * 16);
            off ^= (off >> 3) & 0x70;
            CP_ASYNC16(base + GS_AH + off, Ah + (size_t)(m0 + r) * KDIM + kt + c16 * 8);
            CP_ASYNC16(base + GS_BH + off, Bh + (size_t)(n0 + r) * KDIM + kt + c16 * 8);
        }
        CP_COMMIT();
    };

    auto compute_stage = [&](int s) {
        const uint32_t base = sb + (uint32_t)(s % 3) * GS_STRIDE;
        const int lr = lid & 15;
        const int lc = lid >> 4;
        #pragma unroll
        for (int ks = 0; ks < 4; ks++) {
            uint32_t bf[2][4];
            #pragma unroll
            for (int bt = 0; bt < 2; bt++) {
                uint32_t boff = (uint32_t)((wn * 32 + bt * 16 + lr) * 128 + ks * 32 + lc * 16);
                boff ^= (boff >> 3) & 0x70;
                LDMX4(bf[bt][0], bf[bt][1], bf[bt][2], bf[bt][3], base + GS_BH + boff);
            }
            #pragma unroll
            for (int mt = 0; mt < 4; mt++) {
                uint32_t aoff = (uint32_t)((wm * 64 + mt * 16 + lr) * 128 + ks * 32 + lc * 16);
                aoff ^= (aoff >> 3) & 0x70;
                uint32_t a0, a1, a2, a3;
                LDMX4(a0, a1, a2, a3, base + GS_AH + aoff);
                #pragma unroll
                for (int bt = 0; bt < 2; bt++) {
                    MMA16816(acc[mt][bt * 2],     a0, a1, a2, a3, bf[bt][0], bf[bt][2]);
                    MMA16816(acc[mt][bt * 2 + 1], a0, a1, a2, a3, bf[bt][1], bf[bt][3]);
                }
            }
        }
    };

    issue_stage(0);
    issue_stage(1);
    for (int s = 0; s < NSTG; s++) {
        if (s + 1 < NSTG) CP_WAIT(1); else CP_WAIT(0);
        __syncthreads();
        compute_stage(s);
        if (s + 2 < NSTG) issue_stage(s + 2);
    }

    // ---------------- epilogue ----------------
    const int rrow = lid >> 2;
    const int cpair = (lid & 3) * 2;
    #pragma unroll
    for (int mt = 0; mt < 4; mt++) {
        #pragma unroll
        for (int j = 0; j < 4; j++) {
            int n = n0 + wn * 32 + j * 8 + cpair;
            if (MODE == 0) {
                #pragma unroll
                for (int hf = 0; hf < 2; hf++) {
                    int m = m0 + wm * 64 + mt * 16 + rrow + hf * 8;
                    *(float2*)(Dout + (size_t)m * EMB + n) =
                        make_float2(acc[mt][j][2 * hf], acc[mt][j][2 * hf + 1]);
                }
            } else {
                __half* Dh = (z == 0) ? Dh0 : (z == 1) ? Dh1 : Dh2;
                int h  = n >> 7;
                int dd = n & 127;
                float invf = powf(10000.0f, -(float)(dd >> 1) * (1.0f / 64.0f));
                #pragma unroll
                for (int hf = 0; hf < 2; hf++) {
                    int m = m0 + wm * 64 + mt * 16 + rrow + hf * 8;
                    int bb = m >> 11;
                    int sq = m & 2047;
                    float c0 = acc[mt][j][2 * hf], c1 = acc[mt][j][2 * hf + 1];
                    float v0 = c0, v1 = c1;
                    if (z < 2) {
                        float ang = (float)sq * invf;
                        float sn, cs;
                        sincosf(ang, &sn, &cs);
                        v0 = c0 * cs - c1 * sn;
                        v1 = c1 * cs + c0 * sn;
                    }
                    size_t idx = ((size_t)(bb * NHEAD + h) * SEQ + sq) * HDIM + dd;
                    *(uint32_t*)(Dh + idx) = pack_h2(__float2half_rn(v0), __float2half_rn(v1));
                }
            }
        }
    }
}

// =================================================================================
// Flash attention: S = Qh·Kh (single-pass); O = (Ph+Pl)·Vh
// smem: Qh 32K | 2 x (Kh 16K | Vh 16K) = 96KB
// =================================================================================
#define FQH 0
#define FKV 32768
#define FKV_STRIDE 32768
#define FKH 0
#define FVH 16384
#define FH_BYTES 98304

__device__ __forceinline__ uint32_t sw256(uint32_t off) {
    return off ^ ((off >> 4) & 0x70);
}

__global__ void __launch_bounds__(256, 1) flash_mma(
    const __half* __restrict__ Qh,
    const __half* __restrict__ Kh,
    const __half* __restrict__ Vh,
    __half* __restrict__ Ch)
{
    extern __shared__ char sm[];
    const uint32_t sb = smem_u32(sm);

    const int tid = threadIdx.x;
    const int wid = tid >> 5;
    const int lid = tid & 31;
    const int q0 = (gridDim.x - 1 - blockIdx.x) * 128;
    const int b  = blockIdx.y >> 4, h = blockIdx.y & 15;
    const size_t bh = ((size_t)(b * NHEAD + h)) * SEQ * HDIM;

    const int nIter = (q0 >> 6) + 2;

    auto issue_kv = [&](int it, int buf) {
        const int j0 = it * 64;
        const uint32_t base = sb + FKV + buf * FKV_STRIDE;
        #pragma unroll
        for (int i = 0; i < 4; i++) {
            int c = i * 256 + tid;
            int r = c >> 4, c16 = c & 15;
            uint32_t off = sw256((uint32_t)(r * 256 + c16 * 16));
            size_t src = bh + (size_t)(j0 + r) * HDIM + c16 * 8;
            CP_ASYNC16(base + FKH + off, Kh + src);
            CP_ASYNC16(base + FVH + off, Vh + src);
        }
        CP_COMMIT();
    };

    {
        #pragma unroll
        for (int i = 0; i < 8; i++) {
            int c = i * 256 + tid;
            int r = c >> 4, c16 = c & 15;
            uint32_t off = sw256((uint32_t)(r * 256 + c16 * 16));
            CP_ASYNC16(sb + FQH + off, Qh + bh + (size_t)(q0 + r) * HDIM + c16 * 8);
        }
    }
    issue_kv(0, 0);

    float os[16][4];
    #pragma unroll
    for (int i = 0; i < 16; i++)
        #pragma unroll
        for (int j = 0; j < 4; j++) os[i][j] = 0.f;
    float mrow[2] = {-1e30f, -1e30f};
    float lrow[2] = {0.f, 0.f};
    const float scale = 0.08838834764831845f;

    const int lr = lid & 15;
    const int lc = lid >> 4;

    for (int it = 0; it < nIter; it++) {
        const int j0 = it * 64;
        const int buf = it & 1;
        const uint32_t kbase = sb + FKV + buf * FKV_STRIDE;

        if (it + 1 < nIter) {
            issue_kv(it + 1, buf ^ 1);
            CP_WAIT(1);
        } else {
            CP_WAIT(0);
        }
        __syncthreads();

        if (j0 < q0 + (wid + 1) * 16) {
            float sacc[8][4];
            #pragma unroll
            for (int i = 0; i < 8; i++)
                #pragma unroll
                for (int j = 0; j < 4; j++) sacc[i][j] = 0.f;

            // ---- S = Qh Kh (single-pass) ----
            #pragma unroll
            for (int ks = 0; ks < 8; ks++) {
                uint32_t aoff = sw256((uint32_t)((wid * 16 + lr) * 256 + ks * 32 + lc * 16));
                uint32_t qh0, qh1, qh2, qh3;
                LDMX4(qh0, qh1, qh2, qh3, sb + FQH + aoff);
                #pragma unroll
                for (int bg = 0; bg < 4; bg++) {
                    uint32_t boff = sw256((uint32_t)((bg * 16 + lr) * 256 + ks * 32 + lc * 16));
                    uint32_t kh0, kh1, kh2, kh3;
                    LDMX4(kh0, kh1, kh2, kh3, kbase + FKH + boff);
                    MMA16816(sacc[bg * 2],     qh0, qh1, qh2, qh3, kh0, kh2);
                    MMA16816(sacc[bg * 2 + 1], qh0, qh1, qh2, qh3, kh1, kh3);
                }
            }

            const int r0g = q0 + wid * 16 + (lid >> 2);
            const int c0g = j0 + 2 * (lid & 3);
            #pragma unroll
            for (int nt = 0; nt < 8; nt++)
                #pragma unroll
                for (int c = 0; c < 4; c++) {
                    int rr = r0g + ((c >= 2) ? 8 : 0);
                    int cc = c0g + nt * 8 + (c & 1);
                    float v = sacc[nt][c] * scale;
                    if (cc > rr) v = -1e30f;
                    sacc[nt][c] = v;
                }

            float mx0 = -1e30f, mx1 = -1e30f;
            #pragma unroll
            for (int nt = 0; nt < 8; nt++) {
                mx0 = fmaxf(mx0, fmaxf(sacc[nt][0], sacc[nt][1]));
                mx1 = fmaxf(mx1, fmaxf(sacc[nt][2], sacc[nt][3]));
            }
            #pragma unroll
            for (int o = 1; o < 4; o <<= 1) {
                mx0 = fmaxf(mx0, __shfl_xor_sync(0xffffffffu, mx0, o));
                mx1 = fmaxf(mx1, __shfl_xor_sync(0xffffffffu, mx1, o));
            }
            float mn0 = fmaxf(mrow[0], mx0);
            float mn1 = fmaxf(mrow[1], mx1);
            float cr0 = __expf(mrow[0] - mn0);
            float cr1 = __expf(mrow[1] - mn1);
            float rs0 = 0.f, rs1 = 0.f;
            #pragma unroll
            for (int nt = 0; nt < 8; nt++) {
                float p0 = __expf(sacc[nt][0] - mn0);
                float p1 = __expf(sacc[nt][1] - mn0);
                float p2 = __expf(sacc[nt][2] - mn1);
                float p3 = __expf(sacc[nt][3] - mn1);
                sacc[nt][0] = p0; sacc[nt][1] = p1; sacc[nt][2] = p2; sacc[nt][3] = p3;
                rs0 += p0 + p1; rs1 += p2 + p3;
            }
            #pragma unroll
            for (int o = 1; o < 4; o <<= 1) {
                rs0 += __shfl_xor_sync(0xffffffffu, rs0, o);
                rs1 += __shfl_xor_sync(0xffffffffu, rs1, o);
            }
            lrow[0] = lrow[0] * cr0 + rs0;
            lrow[1] = lrow[1] * cr1 + rs1;
            mrow[0] = mn0; mrow[1] = mn1;
            #pragma unroll
            for (int nt = 0; nt < 16; nt++) {
                os[nt][0] *= cr0; os[nt][1] *= cr0;
                os[nt][2] *= cr1; os[nt][3] *= cr1;
            }

            // ---- O += (Ph + Pl) Vh ----
            #pragma unroll
            for (int kt = 0; kt < 4; kt++) {
                uint32_t ah[4], al[4];
                #pragma unroll
                for (int q = 0; q < 4; q++) {
                    int nt = 2 * kt + (q >> 1);
                    int cc = (q & 1) * 2;
                    split_hl(sacc[nt][cc], sacc[nt][cc + 1], ah[q], al[q]);
                }
                const int vrow = kt * 16 + (lid & 7) + ((lid >> 3) & 1) * 8;
                const int vnh  = (lid >> 4) * 8;
                #pragma unroll
                for (int bg2 = 0; bg2 < 8; bg2++) {
                    uint32_t voff = sw256((uint32_t)(vrow * 256 + (bg2 * 16 + vnh) * 2));
                    uint32_t vh0, vh1, vh2, vh3;
                    LDMX4T(vh0, vh1, vh2, vh3, kbase + FVH + voff);
                    MMA16816(os[bg2 * 2],     ah[0], ah[1], ah[2], ah[3], vh0, vh1);
                    MMA16816(os[bg2 * 2],     al[0], al[1], al[2], al[3], vh0, vh1);
                    MMA16816(os[bg2 * 2 + 1], ah[0], ah[1], ah[2], ah[3], vh2, vh3);
                    MMA16816(os[bg2 * 2 + 1], al[0], al[1], al[2], al[3], vh2, vh3);
                }
            }
        }
        __syncthreads();
    }

    const float inv0 = 1.0f / lrow[0];
    const float inv1 = 1.0f / lrow[1];
    const int row0 = q0 + wid * 16 + (lid >> 2);
    const int dbase = 2 * (lid & 3);
    #pragma unroll
    for (int nt = 0; nt < 16; nt++) {
        int d = nt * 8 + dbase;
        size_t i0 = ((size_t)(b * SEQ + row0))     * EMB + h * HDIM + d;
        size_t i1 = ((size_t)(b * SEQ + row0 + 8)) * EMB + h * HDIM + d;
        *(uint32_t*)(Ch + i0) = pack_h2(__float2half_rn(os[nt][0] * inv0),
                                        __float2half_rn(os[nt][1] * inv0));
        *(uint32_t*)(Ch + i1) = pack_h2(__float2half_rn(os[nt][2] * inv1),
                                        __float2half_rn(os[nt][3] * inv1));
    }
}

// =================================================================================
extern "C" void kernel_launch(void* const* d_in, const int* in_sizes, int n_in,
                              void* d_out, int out_size)
{
    const float* x  = (const float*)d_in[0];
    const float* Wq = (const float*)d_in[1];
    const float* Wk = (const float*)d_in[2];
    const float* Wv = (const float*)d_in[3];
    const float* Wo = (const float*)d_in[4];
    float* out = (float*)d_out;

    __half *xh, *Wh, *Qh, *Kh, *Vh, *Ch;
    cudaGetSymbolAddress((void**)&xh, g_xh);
    cudaGetSymbolAddress((void**)&Wh, g_Wh);
    cudaGetSymbolAddress((void**)&Qh, g_Qh);
    cudaGetSymbolAddress((void**)&Kh, g_Kh);
    cudaGetSymbolAddress((void**)&Vh, g_Vh);
    cudaGetSymbolAddress((void**)&Ch, g_Ch);

    cudaFuncSetAttribute(gemm_hl<1>, cudaFuncAttributeMaxDynamicSharedMemorySize, GSM);
    cudaFuncSetAttribute(gemm_hl<0>, cudaFuncAttributeMaxDynamicSharedMemorySize, GSM);
    cudaFuncSetAttribute(flash_mma, cudaFuncAttributeMaxDynamicSharedMemorySize, FH_BYTES);

    // 0) fused pre-convert
    conv_all<<<XB + 4 * WB, 256>>>(x, Wq, Wk, Wv, Wo, xh, Wh);

    // 1) QKV projection (single-pass fp16, BN=128) + RoPE -> fp16 [B,H,S,D]
    {
        dim3 grid(EMB / BN, MTOT / BM, 3);
        gemm_hl<1><<<grid, 256, GSM>>>(
            xh,
            Wh + 0 * (size_t)NELEM_W,
            Wh + 1 * (size_t)NELEM_W,
            Wh + 2 * (size_t)NELEM_W,
            Qh, Kh, Vh, nullptr);
    }
    // 2) causal flash attention -> context fp16
    {
        dim3 grid(SEQ / 128, BATCH * NHEAD);
        flash_mma<<<grid, 256, FH_BYTES>>>(Qh, Kh, Vh, Ch);
    }
    // 3) output projection (single-pass fp16, BN=128) -> fp32 out
    {
        dim3 grid(EMB / BN, MTOT / BM, 1);
        gemm_hl<0><<<grid, 256, GSM>>>(
            Ch,
            Wh + 3 * (size_t)NELEM_W, nullptr, nullptr,
            nullptr, nullptr, nullptr, out);
    }
}

// round 14
// speedup vs baseline: 2.5575x; 1.0067x over previous
#include <cuda_runtime.h>
#include <cuda_fp16.h>
#include <math.h>
#include <stdint.h>

#define BATCH  4
#define SEQ    2048
#define EMB    2048
#define NHEAD  16
#define HDIM   128
#define MTOT   (BATCH*SEQ)      // 8192
#define KDIM   2048
#define NELEM_X (MTOT*KDIM)     // 16.8M
#define NELEM_W (KDIM*KDIM)     // 4.19M

// ---------------- scratch (device globals: allocation-free rule) ----------------
__device__ __half g_xh[NELEM_X];
__device__ __half g_Wh[4][NELEM_W];
__device__ __half g_Qh[NELEM_X];
__device__ __half g_Kh[NELEM_X];
__device__ __half g_Vh[NELEM_X];
__device__ __half g_Ch[NELEM_X];

__device__ __forceinline__ uint32_t smem_u32(const void* p) {
    uint32_t a;
    asm("{ .reg .u64 t; cvta.to.shared.u64 t, %1; cvt.u32.u64 %0, t; }" : "=r"(a) : "l"(p));
    return a;
}

#define CP_ASYNC16(dst, src) \
    asm volatile("cp.async.cg.shared.global [%0], [%1], 16;" :: "r"(dst), "l"(src))
#define CP_COMMIT() asm volatile("cp.async.commit_group;" ::: "memory")
#define CP_WAIT(n)  asm volatile("cp.async.wait_group %0;" :: "n"(n) : "memory")

#define LDMX4(r0,r1,r2,r3, addr) \
    asm volatile("ldmatrix.sync.aligned.m8n8.x4.shared.b16 {%0,%1,%2,%3}, [%4];" \
        : "=r"(r0),"=r"(r1),"=r"(r2),"=r"(r3) : "r"(addr))
#define LDMX4T(r0,r1,r2,r3, addr) \
    asm volatile("ldmatrix.sync.aligned.m8n8.x4.trans.shared.b16 {%0,%1,%2,%3}, [%4];" \
        : "=r"(r0),"=r"(r1),"=r"(r2),"=r"(r3) : "r"(addr))

#define MMA16816(c, a0,a1,a2,a3, b0,b1) \
    asm volatile("mma.sync.aligned.m16n8k16.row.col.f32.f16.f16.f32 " \
        "{%0,%1,%2,%3}, {%4,%5,%6,%7}, {%8,%9}, {%0,%1,%2,%3};" \
        : "+f"((c)[0]),"+f"((c)[1]),"+f"((c)[2]),"+f"((c)[3]) \
        : "r"(a0),"r"(a1),"r"(a2),"r"(a3), "r"(b0),"r"(b1))

__device__ __forceinline__ uint32_t pack_h2(__half x, __half y) {
    __half2 h = __halves2half2(x, y);
    return *(uint32_t*)&h;
}
__device__ __forceinline__ void split_hl(float x, float y, uint32_t& hp, uint32_t& lp) {
    __half hx = __float2half_rn(x), hy = __float2half_rn(y);
    hp = pack_h2(hx, hy);
    lp = pack_h2(__float2half_rn(x - __half2float(hx)),
                 __float2half_rn(y - __half2float(hy)));
}

// =================================================================================
// fused pre-convert: x and all W -> fp16 (4 x float4 per thread)
// =================================================================================
#define XB (NELEM_X/4096)
#define WB (NELEM_W/4096)

__global__ void __launch_bounds__(256) conv_all(
    const float* __restrict__ x,
    const float* __restrict__ Wq, const float* __restrict__ Wk,
    const float* __restrict__ Wv, const float* __restrict__ Wo,
    __half* __restrict__ xh, __half* __restrict__ Wh)
{
    int blk = blockIdx.x;
    const float* s;
    __half* h;
    if (blk < XB) {
        s = x; h = xh;
    } else {
        int wi = (blk - XB) / WB;
        blk = (blk - XB) % WB;
        s = (wi == 0) ? Wq : (wi == 1) ? Wk : (wi == 2) ? Wv : Wo;
        h = Wh + (size_t)wi * NELEM_W;
    }
    int i0 = blk * 1024 + threadIdx.x;
    #pragma unroll
    for (int k = 0; k < 4; k++) {
        int i = i0 + k * 256;
        float4 v = ((const float4*)s)[i];
        uint2 hp;
        hp.x = pack_h2(__float2half_rn(v.x), __float2half_rn(v.y));
        hp.y = pack_h2(__float2half_rn(v.z), __float2half_rn(v.w));
        ((uint2*)h)[i] = hp;
    }
}

// =================================================================================
// single-pass fp16 mma GEMM (R11/R12 structure; powf RoPE as in R12)
// =================================================================================
#define BM 128
#define BN 128
#define BK 64
#define NSTG (KDIM/BK)     // 32

#define GS_AH 0
#define GS_BH 16384
#define GS_STRIDE 32768
#define GSM (3*GS_STRIDE)   // 96KB

template<int MODE>
__global__ void __launch_bounds__(256, 2) gemm_hl(
    const __half* __restrict__ Ah,
    const __half* __restrict__ Bh0, const __half* __restrict__ Bh1,
    const __half* __restrict__ Bh2,
    __half* __restrict__ Dh0, __half* __restrict__ Dh1, __half* __restrict__ Dh2,
    float* __restrict__ Dout)
{
    extern __shared__ char sm[];
    const uint32_t sb = smem_u32(sm);

    const __half* Bh = Bh0;
    int z = 0;
    if (MODE == 1) {
        z = blockIdx.z;
        if (z == 1) Bh = Bh1;
        else if (z == 2) Bh = Bh2;
    }

    const int tid = threadIdx.x;
    const int wid = tid >> 5;
    const int lid = tid & 31;
    const int wm = wid >> 2;
    const int wn = wid & 3;
    const int m0 = blockIdx.y * BM;
    const int n0 = blockIdx.x * BN;

    float acc[4][4][4];
    #pragma unroll
    for (int i = 0; i < 4; i++)
        #pragma unroll
        for (int j = 0; j < 4; j++)
            #pragma unroll
            for (int k = 0; k < 4; k++) acc[i][j][k] = 0.f;

    auto issue_stage = [&](int s) {
        const int kt = s * BK;
        const uint32_t base = sb + (uint32_t)(s % 3) * GS_STRIDE;
        #pragma unroll
        for (int i = 0; i < 4; i++) {
            int c = i * 256 + tid;
            int r = c >> 3, c16 = c & 7;
            uint32_t off = (uint32_t)(r * 128 + c16 * 16);
            off ^= (off >> 3) & 0x70;
            CP_ASYNC16(base + GS_AH + off, Ah + (size_t)(m0 + r) * KDIM + kt + c16 * 8);
            CP_ASYNC16(base + GS_BH + off, Bh + (size_t)(n0 + r) * KDIM + kt + c16 * 8);
        }
        CP_COMMIT();
    };

    auto compute_stage = [&](int s) {
        const uint32_t base = sb + (uint32_t)(s % 3) * GS_STRIDE;
        const int lr = lid & 15;
        const int lc = lid >> 4;
        #pragma unroll
        for (int ks = 0; ks < 4; ks++) {
            uint32_t bf[2][4];
            #pragma unroll
            for (int bt = 0; bt < 2; bt++) {
                uint32_t boff = (uint32_t)((wn * 32 + bt * 16 + lr) * 128 + ks * 32 + lc * 16);
                boff ^= (boff >> 3) & 0x70;
                LDMX4(bf[bt][0], bf[bt][1], bf[bt][2], bf[bt][3], base + GS_BH + boff);
            }
            #pragma unroll
            for (int mt = 0; mt < 4; mt++) {
                uint32_t aoff = (uint32_t)((wm * 64 + mt * 16 + lr) * 128 + ks * 32 + lc * 16);
                aoff ^= (aoff >> 3) & 0x70;
                uint32_t a0, a1, a2, a3;
                LDMX4(a0, a1, a2, a3, base + GS_AH + aoff);
                #pragma unroll
                for (int bt = 0; bt < 2; bt++) {
                    MMA16816(acc[mt][bt * 2],     a0, a1, a2, a3, bf[bt][0], bf[bt][2]);
                    MMA16816(acc[mt][bt * 2 + 1], a0, a1, a2, a3, bf[bt][1], bf[bt][3]);
                }
            }
        }
    };

    issue_stage(0);
    issue_stage(1);
    for (int s = 0; s < NSTG; s++) {
        if (s + 1 < NSTG) CP_WAIT(1); else CP_WAIT(0);
        __syncthreads();
        compute_stage(s);
        if (s + 2 < NSTG) issue_stage(s + 2);
    }

    // ---------------- epilogue ----------------
    const int rrow = lid >> 2;
    const int cpair = (lid & 3) * 2;
    #pragma unroll
    for (int mt = 0; mt < 4; mt++) {
        #pragma unroll
        for (int j = 0; j < 4; j++) {
            int n = n0 + wn * 32 + j * 8 + cpair;
            if (MODE == 0) {
                #pragma unroll
                for (int hf = 0; hf < 2; hf++) {
                    int m = m0 + wm * 64 + mt * 16 + rrow + hf * 8;
                    *(float2*)(Dout + (size_t)m * EMB + n) =
                        make_float2(acc[mt][j][2 * hf], acc[mt][j][2 * hf + 1]);
                }
            } else {
                __half* Dh = (z == 0) ? Dh0 : (z == 1) ? Dh1 : Dh2;
                int h  = n >> 7;
                int dd = n & 127;
                float invf = powf(10000.0f, -(float)(dd >> 1) * (1.0f / 64.0f));
                #pragma unroll
                for (int hf = 0; hf < 2; hf++) {
                    int m = m0 + wm * 64 + mt * 16 + rrow + hf * 8;
                    int bb = m >> 11;
                    int sq = m & 2047;
                    float c0 = acc[mt][j][2 * hf], c1 = acc[mt][j][2 * hf + 1];
                    float v0 = c0, v1 = c1;
                    if (z < 2) {
                        float ang = (float)sq * invf;
                        float sn, cs;
                        sincosf(ang, &sn, &cs);
                        v0 = c0 * cs - c1 * sn;
                        v1 = c1 * cs + c0 * sn;
                    }
                    size_t idx = ((size_t)(bb * NHEAD + h) * SEQ + sq) * HDIM + dd;
                    *(uint32_t*)(Dh + idx) = pack_h2(__float2half_rn(v0), __float2half_rn(v1));
                }
            }
        }
    }
}

// =================================================================================
// Flash attention: S = Qh·Kh; O = (Ph+Pl)·Vh  (R12 numerics, bit-identical)
// NEW: 3-stage KV ring (one sync/iter) + Q fragments hoisted to registers.
// smem: Qh 32K | 3 x (Kh 16K | Vh 16K) = 128KB
// =================================================================================
#define FQH 0
#define FKV 32768
#define FKV_STRIDE 32768
#define FKH 0
#define FVH 16384
#define FH_BYTES 131072

__device__ __forceinline__ uint32_t sw256(uint32_t off) {
    return off ^ ((off >> 4) & 0x70);
}

__global__ void __launch_bounds__(256, 1) flash_mma(
    const __half* __restrict__ Qh,
    const __half* __restrict__ Kh,
    const __half* __restrict__ Vh,
    __half* __restrict__ Ch)
{
    extern __shared__ char sm[];
    const uint32_t sb = smem_u32(sm);

    const int tid = threadIdx.x;
    const int wid = tid >> 5;
    const int lid = tid & 31;
    const int q0 = (gridDim.x - 1 - blockIdx.x) * 128;
    const int b  = blockIdx.y >> 4, h = blockIdx.y & 15;
    const size_t bh = ((size_t)(b * NHEAD + h)) * SEQ * HDIM;

    const int nIter = (q0 >> 6) + 2;

    auto issue_kv = [&](int it) {
        const int j0 = it * 64;
        const uint32_t base = sb + FKV + (uint32_t)(it % 3) * FKV_STRIDE;
        #pragma unroll
        for (int i = 0; i < 4; i++) {
            int c = i * 256 + tid;
            int r = c >> 4, c16 = c & 15;
            uint32_t off = sw256((uint32_t)(r * 256 + c16 * 16));
            size_t src = bh + (size_t)(j0 + r) * HDIM + c16 * 8;
            CP_ASYNC16(base + FKH + off, Kh + src);
            CP_ASYNC16(base + FVH + off, Vh + src);
        }
        CP_COMMIT();
    };

    // Q (own commit group) then KV0, KV1
    {
        #pragma unroll
        for (int i = 0; i < 8; i++) {
            int c = i * 256 + tid;
            int r = c >> 4, c16 = c & 15;
            uint32_t off = sw256((uint32_t)(r * 256 + c16 * 16));
            CP_ASYNC16(sb + FQH + off, Qh + bh + (size_t)(q0 + r) * HDIM + c16 * 8);
        }
        CP_COMMIT();
    }
    issue_kv(0);
    if (nIter > 1) issue_kv(1);

    // wait for Q, then hoist Q fragments to registers
    const int lr = lid & 15;
    const int lc = lid >> 4;
    uint32_t qf[8][4];
    if (nIter > 1) CP_WAIT(2); else CP_WAIT(1);
    __syncthreads();
    #pragma unroll
    for (int ks = 0; ks < 8; ks++) {
        uint32_t aoff = sw256((uint32_t)((wid * 16 + lr) * 256 + ks * 32 + lc * 16));
        LDMX4(qf[ks][0], qf[ks][1], qf[ks][2], qf[ks][3], sb + FQH + aoff);
    }

    float os[16][4];
    #pragma unroll
    for (int i = 0; i < 16; i++)
        #pragma unroll
        for (int j = 0; j < 4; j++) os[i][j] = 0.f;
    float mrow[2] = {-1e30f, -1e30f};
    float lrow[2] = {0.f, 0.f};
    const float scale = 0.08838834764831845f;

    for (int it = 0; it < nIter; it++) {
        const int j0 = it * 64;
        const uint32_t kbase = sb + FKV + (uint32_t)(it % 3) * FKV_STRIDE;

        if (it + 1 < nIter) CP_WAIT(1); else CP_WAIT(0);
        __syncthreads();     // KV(it) visible; all warps past compute(it-1) -> ring safe

        if (j0 < q0 + (wid + 1) * 16) {
            float sacc[8][4];
            #pragma unroll
            for (int i = 0; i < 8; i++)
                #pragma unroll
                for (int j = 0; j < 4; j++) sacc[i][j] = 0.f;

            // ---- S = Qh Kh ----
            #pragma unroll
            for (int ks = 0; ks < 8; ks++) {
                #pragma unroll
                for (int bg = 0; bg < 4; bg++) {
                    uint32_t boff = sw256((uint32_t)((bg * 16 + lr) * 256 + ks * 32 + lc * 16));
                    uint32_t kh0, kh1, kh2, kh3;
                    LDMX4(kh0, kh1, kh2, kh3, kbase + FKH + boff);
                    MMA16816(sacc[bg * 2],     qf[ks][0], qf[ks][1], qf[ks][2], qf[ks][3], kh0, kh2);
                    MMA16816(sacc[bg * 2 + 1], qf[ks][0], qf[ks][1], qf[ks][2], qf[ks][3], kh1, kh3);
                }
            }

            const int r0g = q0 + wid * 16 + (lid >> 2);
            const int c0g = j0 + 2 * (lid & 3);
            #pragma unroll
            for (int nt = 0; nt < 8; nt++)
                #pragma unroll
                for (int c = 0; c < 4; c++) {
                    int rr = r0g + ((c >= 2) ? 8 : 0);
                    int cc = c0g + nt * 8 + (c & 1);
                    float v = sacc[nt][c] * scale;
                    if (cc > rr) v = -1e30f;
                    sacc[nt][c] = v;
                }

            float mx0 = -1e30f, mx1 = -1e30f;
            #pragma unroll
            for (int nt = 0; nt < 8; nt++) {
                mx0 = fmaxf(mx0, fmaxf(sacc[nt][0], sacc[nt][1]));
                mx1 = fmaxf(mx1, fmaxf(sacc[nt][2], sacc[nt][3]));
            }
            #pragma unroll
            for (int o = 1; o < 4; o <<= 1) {
                mx0 = fmaxf(mx0, __shfl_xor_sync(0xffffffffu, mx0, o));
                mx1 = fmaxf(mx1, __shfl_xor_sync(0xffffffffu, mx1, o));
            }
            float mn0 = fmaxf(mrow[0], mx0);
            float mn1 = fmaxf(mrow[1], mx1);
            float cr0 = __expf(mrow[0] - mn0);
            float cr1 = __expf(mrow[1] - mn1);
            float rs0 = 0.f, rs1 = 0.f;
            #pragma unroll
            for (int nt = 0; nt < 8; nt++) {
                float p0 = __expf(sacc[nt][0] - mn0);
                float p1 = __expf(sacc[nt][1] - mn0);
                float p2 = __expf(sacc[nt][2] - mn1);
                float p3 = __expf(sacc[nt][3] - mn1);
                sacc[nt][0] = p0; sacc[nt][1] = p1; sacc[nt][2] = p2; sacc[nt][3] = p3;
                rs0 += p0 + p1; rs1 += p2 + p3;
            }
            #pragma unroll
            for (int o = 1; o < 4; o <<= 1) {
                rs0 += __shfl_xor_sync(0xffffffffu, rs0, o);
                rs1 += __shfl_xor_sync(0xffffffffu, rs1, o);
            }
            lrow[0] = lrow[0] * cr0 + rs0;
            lrow[1] = lrow[1] * cr1 + rs1;
            mrow[0] = mn0; mrow[1] = mn1;
            #pragma unroll
            for (int nt = 0; nt < 16; nt++) {
                os[nt][0] *= cr0; os[nt][1] *= cr0;
                os[nt][2] *= cr1; os[nt][3] *= cr1;
            }

            // ---- O += (Ph + Pl) Vh ----
            #pragma unroll
            for (int kt = 0; kt < 4; kt++) {
                uint32_t ah[4], al[4];
                #pragma unroll
                for (int q = 0; q < 4; q++) {
                    int nt = 2 * kt + (q >> 1);
                    int cc = (q & 1) * 2;
                    split_hl(sacc[nt][cc], sacc[nt][cc + 1], ah[q], al[q]);
                }
                const int vrow = kt * 16 + (lid & 7) + ((lid >> 3) & 1) * 8;
                const int vnh  = (lid >> 4) * 8;
                #pragma unroll
                for (int bg2 = 0; bg2 < 8; bg2++) {
                    uint32_t voff = sw256((uint32_t)(vrow * 256 + (bg2 * 16 + vnh) * 2));
                    uint32_t vh0, vh1, vh2, vh3;
                    LDMX4T(vh0, vh1, vh2, vh3, kbase + FVH + voff);
                    MMA16816(os[bg2 * 2],     ah[0], ah[1], ah[2], ah[3], vh0, vh1);
                    MMA16816(os[bg2 * 2],     al[0], al[1], al[2], al[3], vh0, vh1);
                    MMA16816(os[bg2 * 2 + 1], ah[0], ah[1], ah[2], ah[3], vh2, vh3);
                    MMA16816(os[bg2 * 2 + 1], al[0], al[1], al[2], al[3], vh2, vh3);
                }
            }
        }
        if (it + 2 < nIter) issue_kv(it + 2);
    }

    const float inv0 = 1.0f / lrow[0];
    const float inv1 = 1.0f / lrow[1];
    const int row0 = q0 + wid * 16 + (lid >> 2);
    const int dbase = 2 * (lid & 3);
    #pragma unroll
    for (int nt = 0; nt < 16; nt++) {
        int d = nt * 8 + dbase;
        size_t i0 = ((size_t)(b * SEQ + row0))     * EMB + h * HDIM + d;
        size_t i1 = ((size_t)(b * SEQ + row0 + 8)) * EMB + h * HDIM + d;
        *(uint32_t*)(Ch + i0) = pack_h2(__float2half_rn(os[nt][0] * inv0),
                                        __float2half_rn(os[nt][1] * inv0));
        *(uint32_t*)(Ch + i1) = pack_h2(__float2half_rn(os[nt][2] * inv1),
                                        __float2half_rn(os[nt][3] * inv1));
    }
}

// =================================================================================
extern "C" void kernel_launch(void* const* d_in, const int* in_sizes, int n_in,
                              void* d_out, int out_size)
{
    const float* x  = (const float*)d_in[0];
    const float* Wq = (const float*)d_in[1];
    const float* Wk = (const float*)d_in[2];
    const float* Wv = (const float*)d_in[3];
    const float* Wo = (const float*)d_in[4];
    float* out = (float*)d_out;

    __half *xh, *Wh, *Qh, *Kh, *Vh, *Ch;
    cudaGetSymbolAddress((void**)&xh, g_xh);
    cudaGetSymbolAddress((void**)&Wh, g_Wh);
    cudaGetSymbolAddress((void**)&Qh, g_Qh);
    cudaGetSymbolAddress((void**)&Kh, g_Kh);
    cudaGetSymbolAddress((void**)&Vh, g_Vh);
    cudaGetSymbolAddress((void**)&Ch, g_Ch);

    cudaFuncSetAttribute(gemm_hl<1>, cudaFuncAttributeMaxDynamicSharedMemorySize, GSM);
    cudaFuncSetAttribute(gemm_hl<0>, cudaFuncAttributeMaxDynamicSharedMemorySize, GSM);
    cudaFuncSetAttribute(flash_mma, cudaFuncAttributeMaxDynamicSharedMemorySize, FH_BYTES);

    // 0) fused pre-convert
    conv_all<<<XB + 4 * WB, 256>>>(x, Wq, Wk, Wv, Wo, xh, Wh);

    // 1) QKV projection + RoPE -> fp16 [B,H,S,D]
    {
        dim3 grid(EMB / BN, MTOT / BM, 3);
        gemm_hl<1><<<grid, 256, GSM>>>(
            xh,
            Wh + 0 * (size_t)NELEM_W,
            Wh + 1 * (size_t)NELEM_W,
            Wh + 2 * (size_t)NELEM_W,
            Qh, Kh, Vh, nullptr);
    }
    // 2) causal flash attention -> context fp16
    {
        dim3 grid(SEQ / 128, BATCH * NHEAD);
        flash_mma<<<grid, 256, FH_BYTES>>>(Qh, Kh, Vh, Ch);
    }
    // 3) output projection -> fp32 out
    {
        dim3 grid(EMB / BN, MTOT / BM, 1);
        gemm_hl<0><<<grid, 256, GSM>>>(
            Ch,
            Wh + 3 * (size_t)NELEM_W, nullptr, nullptr,
            nullptr, nullptr, nullptr, out);
    }
}